// round 14
// baseline (speedup 1.0000x reference)
#include <cuda_runtime.h>
#include <cuda_fp16.h>
#include <cstdint>
#include <cmath>

// Problem constants (fixed by the dataset)
#define EE 800000
#define NN 50000
#define BN_EPS 1e-5f
#define NTILES_E (EE / 128)      // 6250
#define EDGE_GRID 296

// ---------------------------------------------------------------------------
// Scratch (device globals; no runtime allocation)
// ---------------------------------------------------------------------------
__device__ __align__(16) __half g_h1[(size_t)EE * 128];
__device__ __align__(16) __half g_h2[(size_t)EE * 128];
__device__ __align__(16) __half g_o1[(size_t)NN * 128];
__device__ __align__(16) __half g_o2[(size_t)NN * 128];
__device__ __align__(16) float  g_xw[(size_t)NN * 128];   // x @ w1a[128:256]
__device__ __align__(16) float g_agg[(size_t)NN * 128];
__device__ int   g_cnt[NN];
__device__ float g_sum  [512];                  // 4 layers x 128 col sums
__device__ float g_sumsq[512];                  // 4 layers x 128 col sumsq
__device__ __align__(16) float g_scl[256];      // folded scales: [0]=bn1b, [128]=bn2b
__device__ __align__(16) float g_sft[256];      // folded shifts
__device__ __align__(16) __half g_wt16[98304];  // transposed fp16 weights

// weight slice offsets inside g_wt16 (all [n][k] K-major rows)
#define WT_LO  0        // w1a rows   0..127  (K=128)
#define WT_HI  16384    // w1a rows 128..255  (K=128)
#define WT_W1B 32768    // w1b                (K=128)
#define WT_W2A 49152    // w2a                (K=256)
#define WT_W2B 81920    // w2b                (K=128)

// ---------------------------------------------------------------------------
// Helpers
// ---------------------------------------------------------------------------
__device__ __forceinline__ uint32_t packh2(float a, float b) {
    __half2 h = __floats2half2_rn(a, b);
    return *(uint32_t*)&h;
}

__device__ __forceinline__ uint32_t smem_u32(const void* p) {
    return (uint32_t)__cvta_generic_to_shared(p);
}

__device__ __forceinline__ void cp_async16(uint32_t dst, const void* src) {
    asm volatile("cp.async.cg.shared.global [%0], [%1], 16;"
                 :: "r"(dst), "l"(src));
}
__device__ __forceinline__ void cp_commit() {
    asm volatile("cp.async.commit_group;" ::: "memory");
}
__device__ __forceinline__ void cp_wait0() {
    asm volatile("cp.async.wait_group 0;" ::: "memory");
}

__device__ __forceinline__ void red_add_v4(float* p, float4 v) {
    asm volatile("red.global.add.v4.f32 [%0], {%1,%2,%3,%4};"
                 :: "l"(p), "f"(v.x), "f"(v.y), "f"(v.z), "f"(v.w) : "memory");
}

// ldmatrix: four 8x8 b16 matrices (non-transposed)
__device__ __forceinline__ void ldsm_x4(uint32_t& r0, uint32_t& r1,
                                        uint32_t& r2, uint32_t& r3,
                                        uint32_t addr) {
    asm volatile("ldmatrix.sync.aligned.m8n8.x4.shared.b16 {%0,%1,%2,%3}, [%4];"
                 : "=r"(r0), "=r"(r1), "=r"(r2), "=r"(r3) : "r"(addr));
}

// mma.m16n8k16 fp16 in, fp32 accumulate
__device__ __forceinline__ void mma_f16(float* c, const uint32_t* a,
                                        uint32_t b0, uint32_t b1) {
    asm volatile(
        "mma.sync.aligned.m16n8k16.row.col.f32.f16.f16.f32 "
        "{%0,%1,%2,%3}, {%4,%5,%6,%7}, {%8,%9}, {%0,%1,%2,%3};"
        : "+f"(c[0]), "+f"(c[1]), "+f"(c[2]), "+f"(c[3])
        : "r"(a[0]), "r"(a[1]), "r"(a[2]), "r"(a[3]), "r"(b0), "r"(b1));
}

__device__ __forceinline__ void sts_v4(uint32_t dst, uint4 o) {
    asm volatile("st.shared.v4.b32 [%0], {%1,%2,%3,%4};"
                 :: "r"(dst), "r"(o.x), "r"(o.y), "r"(o.z), "r"(o.w));
}

__device__ __forceinline__ uint32_t h2_affine_relu(uint32_t a, uint32_t s,
                                                   uint32_t f, __half2 z2) {
    __half2 r = __hfma2(*(__half2*)&a, *(__half2*)&s, *(__half2*)&f);
    r = __hmax2(r, z2);
    return *(uint32_t*)&r;
}

// ---------------------------------------------------------------------------
// prep: zero accumulators (vectorized) + transpose/convert weights to f16
// (round-12 proven structure)
// ---------------------------------------------------------------------------
__global__ void prep_kernel(float4* __restrict__ agg4, int* __restrict__ cnt,
                            float* __restrict__ sum, float* __restrict__ sumsq,
                            __half* __restrict__ wt,
                            const float* __restrict__ w1a, const float* __restrict__ w1b,
                            const float* __restrict__ w2a, const float* __restrict__ w2b)
{
    int idx = blockIdx.x * blockDim.x + threadIdx.x;
    if (idx < NN * 32) agg4[idx] = make_float4(0.f, 0.f, 0.f, 0.f);
    if (idx < NN)      cnt[idx] = 0;
    if (idx < 512) { sum[idx] = 0.f; sumsq[idx] = 0.f; }
    if (idx < 98304) {
        float v;
        if (idx < 16384) {                        // w1a lo: k 0..127
            int n = idx >> 7, k = idx & 127;
            v = w1a[k * 128 + n];
        } else if (idx < 32768) {                 // w1a hi: k 128..255
            int i = idx - 16384, n = i >> 7, k = i & 127;
            v = w1a[(128 + k) * 128 + n];
        } else if (idx < 49152) {                 // w1b
            int i = idx - 32768, n = i >> 7, k = i & 127;
            v = w1b[k * 128 + n];
        } else if (idx < 81920) {                 // w2a: K=256
            int i = idx - 49152, n = i >> 8, k = i & 255;
            v = w2a[k * 128 + n];
        } else {                                  // w2b
            int i = idx - 81920, n = i >> 7, k = i & 127;
            v = w2b[k * 128 + n];
        }
        wt[idx] = __float2half_rn(v);
    }
}

// fold BN stats into per-feature scale/shift (generic)
__global__ void bnfold_kernel(const float* __restrict__ psum,
                              const float* __restrict__ psq,
                              const float* __restrict__ gamma,
                              const float* __restrict__ beta,
                              float invM,
                              float* __restrict__ scl, float* __restrict__ sft)
{
    int t = threadIdx.x;   // 128
    float m  = psum[t] * invM;
    float v  = fmaxf(psq[t] * invM - m * m, 0.f);
    float sc = gamma[t] * rsqrtf(v + BN_EPS);
    scl[t] = sc;
    sft[t] = beta[t] - m * sc;
}

// ---------------------------------------------------------------------------
// Shared compute core for persistent edge kernel (K=128, 256B smem rows).
// BN=true applies in-fragment affine+relu using half2 scale/shift tables.
// ---------------------------------------------------------------------------
template<bool BN>
__device__ __forceinline__ void compute_steps(
    uint32_t aB, uint32_t bB, float acc[2][8][4],
    const int* rA, const int* rB, int uHi, int t4,
    const __half2* sScl2, const __half2* sSft2, __half2 z2)
{
#pragma unroll
    for (int step = 0; step < 8; step++) {
        const int unit = step * 2 + uHi;
        uint32_t a[2][4];
#pragma unroll
        for (int mi = 0; mi < 2; mi++)
            ldsm_x4(a[mi][0], a[mi][1], a[mi][2], a[mi][3],
                    aB + (uint32_t)(rA[mi] * 256 + ((unit ^ (rA[mi] & 7)) << 4)));
        if (BN) {
            int b = step * 8 + t4;
            uint32_t cl = *(const uint32_t*)(sScl2 + b);
            uint32_t fl = *(const uint32_t*)(sSft2 + b);
            uint32_t ch = *(const uint32_t*)(sScl2 + b + 4);
            uint32_t fh = *(const uint32_t*)(sSft2 + b + 4);
#pragma unroll
            for (int mi = 0; mi < 2; mi++) {
                a[mi][0] = h2_affine_relu(a[mi][0], cl, fl, z2);
                a[mi][1] = h2_affine_relu(a[mi][1], cl, fl, z2);
                a[mi][2] = h2_affine_relu(a[mi][2], ch, fh, z2);
                a[mi][3] = h2_affine_relu(a[mi][3], ch, fh, z2);
            }
        }
#pragma unroll
        for (int p = 0; p < 4; p++) {
            uint32_t b0, b1, b2, b3;
            ldsm_x4(b0, b1, b2, b3,
                    bB + (uint32_t)(rB[p] * 256 + ((unit ^ (rB[p] & 7)) << 4)));
#pragma unroll
            for (int mi = 0; mi < 2; mi++) {
                mma_f16(acc[mi][2 * p],     a[mi], b0, b2);
                mma_f16(acc[mi][2 * p + 1], a[mi], b1, b3);
            }
        }
    }
}

// stats shuffle-reduce + smem atomics (padless tiles)
__device__ __forceinline__ void stats_reduce(
    float acc[2][8][4], int lane, int t4, int wcc,
    float* sSum, float* sSq)
{
#pragma unroll
    for (int ni = 0; ni < 8; ni++) {
        float s0 = 0, q0 = 0, s1 = 0, q1 = 0;
#pragma unroll
        for (int mi = 0; mi < 2; mi++) {
            float a0 = acc[mi][ni][0], a2 = acc[mi][ni][2];
            float a1 = acc[mi][ni][1], a3 = acc[mi][ni][3];
            s0 += a0 + a2; q0 += a0 * a0 + a2 * a2;
            s1 += a1 + a3; q1 += a1 * a1 + a3 * a3;
        }
#pragma unroll
        for (int off = 4; off < 32; off <<= 1) {
            s0 += __shfl_xor_sync(0xFFFFFFFFu, s0, off);
            q0 += __shfl_xor_sync(0xFFFFFFFFu, q0, off);
            s1 += __shfl_xor_sync(0xFFFFFFFFu, s1, off);
            q1 += __shfl_xor_sync(0xFFFFFFFFu, q1, off);
        }
        if (lane < 4) {
            int c0 = wcc + ni * 8 + 2 * t4;
            atomicAdd(&sSum[c0],     s0); atomicAdd(&sSq[c0],     q0);
            atomicAdd(&sSum[c0 + 1], s1); atomicAdd(&sSq[c0 + 1], q1);
        }
    }
}

// epilogue: acc -> f16 smem staging (256B rows, swizzled) -> coalesced STG
__device__ __forceinline__ void epi_store(
    char* epi, __half* Hout, int bm, int tid, int g, int t4,
    int wr, int wcc, float acc[2][8][4])
{
#pragma unroll
    for (int mi = 0; mi < 2; mi++) {
        int r0 = wr + mi * 16 + g;
        int r1 = r0 + 8;
#pragma unroll
        for (int ni = 0; ni < 8; ni++) {
            int col = wcc + ni * 8 + 2 * t4;
            *(uint32_t*)(epi + r0 * 256 + ((col * 2) ^ ((r0 & 7) << 5))) =
                packh2(acc[mi][ni][0], acc[mi][ni][1]);
            *(uint32_t*)(epi + r1 * 256 + ((col * 2) ^ ((r1 & 7) << 5))) =
                packh2(acc[mi][ni][2], acc[mi][ni][3]);
        }
    }
    __syncthreads();
#pragma unroll
    for (int i = 0; i < 8; i++) {
        int gid = tid + i * 256;
        int row = gid >> 4;
        int seg = gid & 15;
        uint4 v = *(uint4*)(epi + row * 256 + ((seg * 16) ^ ((row & 7) << 5)));
        *(uint4*)(Hout + (size_t)(bm + row) * 128 + seg * 8) = v;
    }
}

// ---------------------------------------------------------------------------
// Persistent edge GEMM 2 (M=128 tiles, round-10 proven): h2 = relu(bn(h1))@w1b
// A via cp.async (f16), BN+relu in-fragment. smem: A0|A1|B (96KB), 2 CTA/SM.
// ---------------------------------------------------------------------------
__launch_bounds__(256, 2)
__global__ void gemm_edge2(
    const __half* __restrict__ h1,
    const float*  __restrict__ psum, const float* __restrict__ psq,
    const float*  __restrict__ gamma, const float* __restrict__ beta,
    const __half* __restrict__ Wt,     // WT_W1B slice
    __half* __restrict__ Hout,
    float* __restrict__ osum, float* __restrict__ osq)
{
    extern __shared__ char dyns[];
    const uint32_t raw   = smem_u32(dyns);
    const uint32_t sbase = (raw + 1023u) & ~1023u;
    char* gbase = dyns + (sbase - raw);
    const uint32_t bB = sbase + 65536u;

    __shared__ __half2 sScl2[64], sSft2[64];
    __shared__ float sSum[128], sSq[128];

    const int tid  = threadIdx.x;
    const int warp = tid >> 5;
    const int lane = tid & 31;
    const int g    = lane >> 2;
    const int t4   = lane & 3;
    const int wr   = (warp & 3) * 32;
    const int wcc  = (warp >> 2) * 64;
    const int uHi  = (lane >> 4);

    if (tid < 128) { sSum[tid] = 0.f; sSq[tid] = 0.f; }
    if (tid < 64) {
        const float invM = 1.0f / EE;
        int k0 = 2 * tid, k1 = k0 + 1;
        float m0 = psum[k0] * invM;
        float v0 = fmaxf(psq[k0] * invM - m0 * m0, 0.f);
        float s0 = gamma[k0] * rsqrtf(v0 + BN_EPS);
        float f0 = beta[k0] - m0 * s0;
        float m1 = psum[k1] * invM;
        float v1 = fmaxf(psq[k1] * invM - m1 * m1, 0.f);
        float s1 = gamma[k1] * rsqrtf(v1 + BN_EPS);
        float f1 = beta[k1] - m1 * s1;
        sScl2[tid] = __floats2half2_rn(s0, s1);
        sSft2[tid] = __floats2half2_rn(f0, f1);
    }

    int rA[2], rB[4];
#pragma unroll
    for (int mi = 0; mi < 2; mi++)
        rA[mi] = wr + mi * 16 + (lane & 7) + ((lane >> 3) & 1) * 8;
#pragma unroll
    for (int p = 0; p < 4; p++)
        rB[p] = wcc + p * 16 + (lane & 7) + ((lane >> 3) & 1) * 8;

    auto cpA = [&](int t, int s) {
        const uint32_t aB = sbase + (uint32_t)s * 32768u;
#pragma unroll
        for (int j = 0; j < 8; j++) {
            int u = tid + j * 256, row = u >> 4, unit = u & 15;
            cp_async16(aB + (uint32_t)(row * 256 + ((unit ^ (row & 7)) << 4)),
                       h1 + (size_t)(t * 128 + row) * 128 + unit * 8);
        }
        cp_commit();
    };

    // prologue: B + A(t0) in one group
#pragma unroll
    for (int j = 0; j < 8; j++) {
        int u = tid + j * 256, n = u >> 4, unit = u & 15;
        cp_async16(bB + (uint32_t)(n * 256 + ((unit ^ (n & 7)) << 4)),
                   Wt + (size_t)n * 128 + unit * 8);
    }
    int t0 = blockIdx.x;
    if (t0 < NTILES_E) {
#pragma unroll
        for (int j = 0; j < 8; j++) {
            int u = tid + j * 256, row = u >> 4, unit = u & 15;
            cp_async16(sbase + (uint32_t)(row * 256 + ((unit ^ (row & 7)) << 4)),
                       h1 + (size_t)(t0 * 128 + row) * 128 + unit * 8);
        }
    }
    cp_commit();

    const __half2 z2 = __floats2half2_rn(0.f, 0.f);
    int i = 0;
    for (int t = t0; t < NTILES_E; t += gridDim.x, i++) {
        const int s  = i & 1;
        const uint32_t aB = sbase + (uint32_t)s * 32768u;
        char* epi = gbase + s * 32768;

        cp_wait0();
        __syncthreads();                              // A(t) (+B first) visible

        int tn = t + gridDim.x;
        if (tn < NTILES_E) cpA(tn, s ^ 1);

        float acc[2][8][4];
#pragma unroll
        for (int mi = 0; mi < 2; mi++)
#pragma unroll
            for (int ni = 0; ni < 8; ni++)
#pragma unroll
                for (int v = 0; v < 4; v++) acc[mi][ni][v] = 0.0f;

        compute_steps<true>(aB, bB, acc, rA, rB, uHi, t4, sScl2, sSft2, z2);
        stats_reduce(acc, lane, t4, wcc, sSum, sSq);
        __syncthreads();                              // A_s reads done
        epi_store(epi, Hout, t * 128, tid, g, t4, wr, wcc, acc);
    }

    __syncthreads();
    if (tid < 128) {
        atomicAdd(osum + tid, sSum[tid]);
        atomicAdd(osq  + tid, sSq[tid]);
    }
}

// ---------------------------------------------------------------------------
// Tiled GEMM (round-8 proven): out[M,128] = A[M,K] @ W[K,128] + fused stats.
// MODE 0: A = message (K=128); epilogue acc += xw[row[r]] BEFORE stats
// MODE 1: A = relu(prev*scale + shift)     (K=128, f16 source)
// MODE 2: A = concat(x, agg_sum*inv_cnt)   (K=256, f32 sources)
// MODE 3: A = x (K=128, f32); plain gemm, f32 out, no stats (xw precompute)
// ---------------------------------------------------------------------------
template<int MODE>
__launch_bounds__(256, 2)
__global__ void gemm_f16(
    const float*  __restrict__ A0f,
    const float*  __restrict__ A1f,
    const __half* __restrict__ A0h,
    const float*  __restrict__ xw,
    const int*    __restrict__ ridx,
    const int*    __restrict__ cnt,
    const float*  __restrict__ psum,
    const float*  __restrict__ psq,
    const float*  __restrict__ gamma,
    const float*  __restrict__ beta,
    float         invPrevM,
    const __half* __restrict__ Wt,
    __half* __restrict__ Hout,
    float*  __restrict__ Hout32,
    int M,
    float* __restrict__ osum,
    float* __restrict__ osq)
{
    constexpr int K   = (MODE == 2) ? 256 : 128;
    constexpr int NIT = K / 64;

    extern __shared__ char dyns[];
    const uint32_t raw   = smem_u32(dyns);
    const uint32_t sbase = (raw + 1023u) & ~1023u;
    char* gbase = dyns + (sbase - raw);

    __shared__ int   sRow[128];
    __shared__ float sInv[128], sScl[128], sSft[128];
    __shared__ float sSum[128], sSq[128];

    const int tid  = threadIdx.x;
    const int warp = tid >> 5;
    const int lane = tid & 31;
    const int bm   = blockIdx.x * 128;

    if (tid < 128) { sSum[tid] = 0.f; sSq[tid] = 0.f; }
    if (MODE == 0 && tid < 128) sRow[tid] = ridx[bm + tid];
    if (MODE == 2 && tid < 128) {
        int r = bm + tid;
        int c = (r < M) ? cnt[r] : 1;
        sInv[tid] = 1.0f / (float)(c > 1 ? c : 1);
    }
    if (MODE == 1 && tid < 128) {
        float m  = psum[tid] * invPrevM;
        float v  = fmaxf(psq[tid] * invPrevM - m * m, 0.f);
        float sc = gamma[tid] * rsqrtf(v + BN_EPS);
        sScl[tid] = sc;
        sSft[tid] = beta[tid] - m * sc;
    }
    __syncthreads();

    auto ldgA = [&](int it, float4* pf, uint4* ph) {
        const int k0 = it * 64;
#pragma unroll
        for (int j = 0; j < 4; j++) {
            int u = tid + j * 256, row = u >> 3, unit = u & 7;
            int kg = k0 + unit * 8;
            int rg = bm + row;
            if (MODE == 1) {
                ph[j] = (rg < M) ? *(const uint4*)(A0h + (size_t)rg * 128 + kg)
                                 : make_uint4(0, 0, 0, 0);
            } else if (MODE == 0) {
                const float* src = A0f + (size_t)rg * 128 + kg;  // EE % 128 == 0
                pf[2 * j]     = *(const float4*)src;
                pf[2 * j + 1] = *(const float4*)(src + 4);
            } else {
                if (rg < M) {
                    const float* src = (MODE == 3 || kg < 128)
                        ? (A0f + (size_t)rg * 128 + kg)
                        : (A1f + (size_t)rg * 128 + (kg - 128));
                    pf[2 * j]     = *(const float4*)src;
                    pf[2 * j + 1] = *(const float4*)(src + 4);
                } else {
                    pf[2 * j]     = make_float4(0, 0, 0, 0);
                    pf[2 * j + 1] = make_float4(0, 0, 0, 0);
                }
            }
        }
    };

    auto stsA = [&](int it, int s, const float4* pf, const uint4* ph) {
        const int k0 = it * 64;
        const uint32_t aB = sbase + (uint32_t)s * 16384u;
#pragma unroll
        for (int j = 0; j < 4; j++) {
            int u = tid + j * 256, row = u >> 3, unit = u & 7;
            int kg = k0 + unit * 8;
            int rg = bm + row;
            uint32_t dst = aB + (uint32_t)(row * 128 + ((unit ^ (row & 7)) << 4));
            uint4 o;
            if (MODE == 0) {
                float4 p = pf[2 * j], q = pf[2 * j + 1];
                o.x = packh2(p.x, p.y); o.y = packh2(p.z, p.w);
                o.z = packh2(q.x, q.y); o.w = packh2(q.z, q.w);
            } else if (MODE == 1) {
                if (rg < M) {
                    uint4 rv = ph[j];
                    float4 sc0 = *(const float4*)(sScl + kg);
                    float4 sc1 = *(const float4*)(sScl + kg + 4);
                    float4 sf0 = *(const float4*)(sSft + kg);
                    float4 sf1 = *(const float4*)(sSft + kg + 4);
                    float2 v0 = __half22float2(*(__half2*)&rv.x);
                    float2 v1 = __half22float2(*(__half2*)&rv.y);
                    float2 v2 = __half22float2(*(__half2*)&rv.z);
                    float2 v3 = __half22float2(*(__half2*)&rv.w);
                    o.x = packh2(fmaxf(fmaf(v0.x, sc0.x, sf0.x), 0.f),
                                 fmaxf(fmaf(v0.y, sc0.y, sf0.y), 0.f));
                    o.y = packh2(fmaxf(fmaf(v1.x, sc0.z, sf0.z), 0.f),
                                 fmaxf(fmaf(v1.y, sc0.w, sf0.w), 0.f));
                    o.z = packh2(fmaxf(fmaf(v2.x, sc1.x, sf1.x), 0.f),
                                 fmaxf(fmaf(v2.y, sc1.y, sf1.y), 0.f));
                    o.w = packh2(fmaxf(fmaf(v3.x, sc1.z, sf1.z), 0.f),
                                 fmaxf(fmaf(v3.y, sc1.w, sf1.w), 0.f));
                } else {
                    o = make_uint4(0, 0, 0, 0);
                }
            } else {
                if (rg < M) {
                    float4 p = pf[2 * j], q = pf[2 * j + 1];
                    if (MODE == 2 && kg >= 128) {
                        float iv = sInv[row];
                        p.x *= iv; p.y *= iv; p.z *= iv; p.w *= iv;
                        q.x *= iv; q.y *= iv; q.z *= iv; q.w *= iv;
                    }
                    o.x = packh2(p.x, p.y); o.y = packh2(p.z, p.w);
                    o.z = packh2(q.x, q.y); o.w = packh2(q.z, q.w);
                } else {
                    o = make_uint4(0, 0, 0, 0);
                }
            }
            sts_v4(dst, o);
        }
    };

    auto cpB = [&](int it, int s) {
        const int k0 = it * 64;
        const uint32_t bB = sbase + 32768u + (uint32_t)s * 16384u;
#pragma unroll
        for (int j = 0; j < 4; j++) {
            int u = tid + j * 256, n = u >> 3, unit = u & 7;
            uint32_t dst = bB + (uint32_t)(n * 128 + ((unit ^ (n & 7)) << 4));
            cp_async16(dst, Wt + (size_t)n * K + k0 + unit * 8);
        }
        cp_commit();
    };

    float acc[2][8][4];
#pragma unroll
    for (int mi = 0; mi < 2; mi++)
#pragma unroll
        for (int ni = 0; ni < 8; ni++)
#pragma unroll
            for (int v = 0; v < 4; v++) acc[mi][ni][v] = 0.0f;

    const int g   = lane >> 2;
    const int t4  = lane & 3;
    const int wm  = warp & 3;
    const int wn  = warp >> 2;
    const int wr  = wm * 32;
    const int wcc = wn * 64;

    int rA[2], rB[4];
#pragma unroll
    for (int mi = 0; mi < 2; mi++)
        rA[mi] = wr + mi * 16 + (lane & 7) + ((lane >> 3) & 1) * 8;
#pragma unroll
    for (int p = 0; p < 4; p++)
        rB[p] = wcc + p * 16 + (lane & 7) + ((lane >> 3) & 1) * 8;
    const int uHi = (lane >> 4);

    {
        float4 pf[8]; uint4 ph[4];
        ldgA(0, pf, ph);
        stsA(0, 0, pf, ph);
        cpB(0, 0);
    }

#pragma unroll 1
    for (int it = 0; it < NIT; it++) {
        const int s = it & 1;
        cp_wait0();
        __syncthreads();

        float4 pf[8]; uint4 ph[4];
        const bool more = (it + 1 < NIT);
        if (more) {
            ldgA(it + 1, pf, ph);
            cpB(it + 1, s ^ 1);
        }

        const uint32_t aB = sbase + (uint32_t)s * 16384u;
        const uint32_t bB = sbase + 32768u + (uint32_t)s * 16384u;

#pragma unroll
        for (int step = 0; step < 4; step++) {
            const int unit = step * 2 + uHi;
            uint32_t a[2][4];
#pragma unroll
            for (int mi = 0; mi < 2; mi++)
                ldsm_x4(a[mi][0], a[mi][1], a[mi][2], a[mi][3],
                        aB + (uint32_t)(rA[mi] * 128 + ((unit ^ (rA[mi] & 7)) << 4)));
#pragma unroll
            for (int p = 0; p < 4; p++) {
                uint32_t b0, b1, b2, b3;
                ldsm_x4(b0, b1, b2, b3,
                        bB + (uint32_t)(rB[p] * 128 + ((unit ^ (rB[p] & 7)) << 4)));
#pragma unroll
                for (int mi = 0; mi < 2; mi++) {
                    mma_f16(acc[mi][2 * p],     a[mi], b0, b2);
                    mma_f16(acc[mi][2 * p + 1], a[mi], b1, b3);
                }
            }
        }

        if (more) stsA(it + 1, s ^ 1, pf, ph);
    }

    // ---- MODE 0: add per-node xw contribution BEFORE stats ----
    if (MODE == 0) {
#pragma unroll
        for (int mi = 0; mi < 2; mi++) {
            const float* x0 = xw + (size_t)sRow[wr + mi * 16 + g]     * 128;
            const float* x1 = xw + (size_t)sRow[wr + mi * 16 + g + 8] * 128;
#pragma unroll
            for (int ni = 0; ni < 8; ni++) {
                int col = wcc + ni * 8 + 2 * t4;
                float2 u0 = *(const float2*)(x0 + col);
                float2 u1 = *(const float2*)(x1 + col);
                acc[mi][ni][0] += u0.x; acc[mi][ni][1] += u0.y;
                acc[mi][ni][2] += u1.x; acc[mi][ni][3] += u1.y;
            }
        }
    }

    if (MODE != 3) {
#pragma unroll
        for (int ni = 0; ni < 8; ni++) {
            float s0 = 0, q0 = 0, s1 = 0, q1 = 0;
#pragma unroll
            for (int mi = 0; mi < 2; mi++) {
                float a0 = acc[mi][ni][0], a2 = acc[mi][ni][2];
                float a1 = acc[mi][ni][1], a3 = acc[mi][ni][3];
                s0 += a0 + a2; q0 += a0 * a0 + a2 * a2;
                s1 += a1 + a3; q1 += a1 * a1 + a3 * a3;
            }
#pragma unroll
            for (int off = 4; off < 32; off <<= 1) {
                s0 += __shfl_xor_sync(0xFFFFFFFFu, s0, off);
                q0 += __shfl_xor_sync(0xFFFFFFFFu, q0, off);
                s1 += __shfl_xor_sync(0xFFFFFFFFu, s1, off);
                q1 += __shfl_xor_sync(0xFFFFFFFFu, q1, off);
            }
            if (lane < 4) {
                int c0 = wcc + ni * 8 + 2 * t4;
                atomicAdd(&sSum[c0],     s0); atomicAdd(&sSq[c0],     q0);
                atomicAdd(&sSum[c0 + 1], s1); atomicAdd(&sSq[c0 + 1], q1);
            }
        }
    }

    __syncthreads();
    char* epi = gbase;

    if (MODE == 3) {
#pragma unroll
        for (int mi = 0; mi < 2; mi++) {
            int r0 = wr + mi * 16 + g;
            int r1 = r0 + 8;
#pragma unroll
            for (int ni = 0; ni < 8; ni++) {
                int col = wcc + ni * 8 + 2 * t4;
                *(float2*)(epi + r0 * 512 + ((col * 4) ^ ((r0 & 7) << 5))) =
                    make_float2(acc[mi][ni][0], acc[mi][ni][1]);
                *(float2*)(epi + r1 * 512 + ((col * 4) ^ ((r1 & 7) << 5))) =
                    make_float2(acc[mi][ni][2], acc[mi][ni][3]);
            }
        }
        __syncthreads();
#pragma unroll
        for (int i = 0; i < 16; i++) {
            int gid = tid + i * 256;
            int row = gid >> 5;
            int seg = gid & 31;
            if (bm + row < M) {
                uint4 v = *(uint4*)(epi + row * 512 + ((seg * 16) ^ ((row & 7) << 5)));
                *(uint4*)(Hout32 + (size_t)(bm + row) * 128 + seg * 4) = v;
            }
        }
        return;
    }

#pragma unroll
    for (int mi = 0; mi < 2; mi++) {
        int r0 = wr + mi * 16 + g;
        int r1 = r0 + 8;
#pragma unroll
        for (int ni = 0; ni < 8; ni++) {
            int col = wcc + ni * 8 + 2 * t4;
            *(uint32_t*)(epi + r0 * 256 + ((col * 2) ^ ((r0 & 7) << 5))) =
                packh2(acc[mi][ni][0], acc[mi][ni][1]);
            *(uint32_t*)(epi + r1 * 256 + ((col * 2) ^ ((r1 & 7) << 5))) =
                packh2(acc[mi][ni][2], acc[mi][ni][3]);
        }
    }
    __syncthreads();
#pragma unroll
    for (int i = 0; i < 8; i++) {
        int gid = tid + i * 256;
        int row = gid >> 4;
        int seg = gid & 15;
        if (bm + row < M) {
            uint4 v = *(uint4*)(epi + row * 256 + ((seg * 16) ^ ((row & 7) << 5)));
            *(uint4*)(Hout + (size_t)(bm + row) * 128 + seg * 8) = v;
        }
    }

    if (tid < 128) {
        atomicAdd(osum + tid, sSum[tid]);
        atomicAdd(osq  + tid, sSq[tid]);
    }
}

// ---------------------------------------------------------------------------
// Scatter: agg[col[e]] += relu(bn(h2_f16[e])), cnt[col[e]] += 1
// 16 edges per warp, 128 edges per block; BN fold pre-computed.
// ---------------------------------------------------------------------------
__global__ void scatter_kernel(const __half* __restrict__ h2,
                               const int* __restrict__ col,
                               const float* __restrict__ scl,
                               const float* __restrict__ sft,
                               float* __restrict__ agg, int* __restrict__ cnt)
{
    const int t    = threadIdx.x;        // 256
    const int warp = t >> 5;
    const int lane = t & 31;

    const float4 sc = __ldg((const float4*)(scl + lane * 4));
    const float4 sf = __ldg((const float4*)(sft + lane * 4));

    const int e0 = blockIdx.x * 128 + warp * 16;
#pragma unroll
    for (int i = 0; i < 16; i++) {
        int e = e0 + i;
        int c = __ldg(col + e);
        uint2 rawv = *(const uint2*)(h2 + (size_t)e * 128 + lane * 4);
        float2 a = __half22float2(*(__half2*)&rawv.x);
        float2 b = __half22float2(*(__half2*)&rawv.y);
        float4 v;
        v.x = fmaxf(fmaf(a.x, sc.x, sf.x), 0.f);
        v.y = fmaxf(fmaf(a.y, sc.y, sf.y), 0.f);
        v.z = fmaxf(fmaf(b.x, sc.z, sf.z), 0.f);
        v.w = fmaxf(fmaf(b.y, sc.w, sf.w), 0.f);
        red_add_v4(agg + (size_t)c * 128 + lane * 4, v);
        if (lane == 0) atomicAdd(cnt + c, 1);
    }
}

// ---------------------------------------------------------------------------
// Final: o = relu(bn(o2)); attn = sigmoid(o @ wa + ba)
// One warp per node (8 nodes/block, no block barrier), fold pre-computed.
// ---------------------------------------------------------------------------
__global__ void output_kernel(const __half* __restrict__ o2,
                              const float* __restrict__ scl,
                              const float* __restrict__ sft,
                              const float* __restrict__ wa,
                              const float* __restrict__ ba,
                              float* __restrict__ out)
{
    const int warp = threadIdx.x >> 5;
    const int lane = threadIdx.x & 31;
    const int n    = blockIdx.x * 8 + warp;   // NN % 8 == 0

    const float4 sc = __ldg((const float4*)(scl + lane * 4));
    const float4 sf = __ldg((const float4*)(sft + lane * 4));
    const float4 w  = __ldg((const float4*)(wa  + lane * 4));

    uint2 rawv = *(const uint2*)(o2 + (size_t)n * 128 + lane * 4);
    float2 a = __half22float2(*(__half2*)&rawv.x);
    float2 b = __half22float2(*(__half2*)&rawv.y);
    float4 v;
    v.x = fmaxf(fmaf(a.x, sc.x, sf.x), 0.f);
    v.y = fmaxf(fmaf(a.y, sc.y, sf.y), 0.f);
    v.z = fmaxf(fmaf(b.x, sc.z, sf.z), 0.f);
    v.w = fmaxf(fmaf(b.y, sc.w, sf.w), 0.f);
    *(float4*)(out + (size_t)n * 128 + lane * 4) = v;

    float p = v.x * w.x + v.y * w.y + v.z * w.z + v.w * w.w;
#pragma unroll
    for (int off = 16; off > 0; off >>= 1)
        p += __shfl_xor_sync(0xFFFFFFFFu, p, off);
    if (lane == 0)
        out[(size_t)NN * 128 + n] = 1.0f / (1.0f + expf(-(p + __ldg(ba))));
}

// ---------------------------------------------------------------------------
// Launch
// ---------------------------------------------------------------------------
#define GEMM_SMEM (65536 + 1024)
#define EDGE_SMEM (98304 + 1024)

extern "C" void kernel_launch(void* const* d_in, const int* in_sizes, int n_in,
                              void* d_out, int out_size)
{
    const float* x       = (const float*)d_in[0];
    const int*   ei      = (const int*)  d_in[1];   // [2,E]: row then col
    const float* message = (const float*)d_in[2];
    const float* w1a  = (const float*)d_in[3];
    const float* g1a  = (const float*)d_in[5];
    const float* be1a = (const float*)d_in[6];
    const float* w1b  = (const float*)d_in[7];
    const float* g1b  = (const float*)d_in[9];
    const float* be1b = (const float*)d_in[10];
    const float* w2a  = (const float*)d_in[11];
    const float* g2a  = (const float*)d_in[13];
    const float* be2a = (const float*)d_in[14];
    const float* w2b  = (const float*)d_in[15];
    const float* g2b  = (const float*)d_in[17];
    const float* be2b = (const float*)d_in[18];
    const float* wa   = (const float*)d_in[19];
    const float* ba   = (const float*)d_in[20];
    float* out = (float*)d_out;

    __half *h1, *h2, *o1, *o2, *wt;
    float *agg, *sum, *sumsq, *xw, *scl, *sft;
    int* cnt;
    cudaGetSymbolAddress((void**)&h1,    g_h1);
    cudaGetSymbolAddress((void**)&h2,    g_h2);
    cudaGetSymbolAddress((void**)&o1,    g_o1);
    cudaGetSymbolAddress((void**)&o2,    g_o2);
    cudaGetSymbolAddress((void**)&xw,    g_xw);
    cudaGetSymbolAddress((void**)&agg,   g_agg);
    cudaGetSymbolAddress((void**)&cnt,   g_cnt);
    cudaGetSymbolAddress((void**)&sum,   g_sum);
    cudaGetSymbolAddress((void**)&sumsq, g_sumsq);
    cudaGetSymbolAddress((void**)&scl,   g_scl);
    cudaGetSymbolAddress((void**)&sft,   g_sft);
    cudaGetSymbolAddress((void**)&wt,    g_wt16);

    const int* row = ei;
    const int* col = ei + EE;

    static bool attr_done = false;
    if (!attr_done) {
        cudaFuncSetAttribute(gemm_f16<0>, cudaFuncAttributeMaxDynamicSharedMemorySize, GEMM_SMEM);
        cudaFuncSetAttribute(gemm_f16<1>, cudaFuncAttributeMaxDynamicSharedMemorySize, GEMM_SMEM);
        cudaFuncSetAttribute(gemm_f16<2>, cudaFuncAttributeMaxDynamicSharedMemorySize, GEMM_SMEM);
        cudaFuncSetAttribute(gemm_f16<3>, cudaFuncAttributeMaxDynamicSharedMemorySize, GEMM_SMEM);
        cudaFuncSetAttribute(gemm_edge2, cudaFuncAttributeMaxDynamicSharedMemorySize, EDGE_SMEM);
        attr_done = true;
    }

    prep_kernel<<<(NN * 32 + 1023) / 1024, 1024>>>((float4*)agg, cnt, sum, sumsq,
                                                   wt, w1a, w1b, w2a, w2b);

    // xw = x @ w1a[128:256]  (f32 out, no stats)
    gemm_f16<3><<<(NN + 127) / 128, 256, GEMM_SMEM>>>(x, nullptr, nullptr, nullptr,
                                 nullptr, nullptr, nullptr, nullptr, nullptr, nullptr, 0.f,
                                 wt + WT_HI, nullptr, xw, NN, nullptr, nullptr);

    // edge layer 1 (round-8 proven): h1 = message @ w1a_lo + xw[row]  (+slot 0)
    gemm_f16<0><<<EE / 128, 256, GEMM_SMEM>>>(message, nullptr, nullptr, xw, row,
                                 nullptr, nullptr, nullptr, nullptr, nullptr, 0.f,
                                 wt + WT_LO, h1, nullptr, EE, sum + 0, sumsq + 0);

    // edge layer 2 (persistent M=128, proven): h2 = relu(bn1a(h1)) @ w1b
    gemm_edge2<<<EDGE_GRID, 256, EDGE_SMEM>>>(h1, sum + 0, sumsq + 0, g1a, be1a,
                                              wt + WT_W1B, h2, sum + 128, sumsq + 128);

    // fold bn1b stats once, then scatter (16 edges/warp, 128 edges/block)
    bnfold_kernel<<<1, 128>>>(sum + 128, sumsq + 128, g1b, be1b, 1.0f / EE,
                              scl + 0, sft + 0);
    scatter_kernel<<<EE / 128, 256>>>(h2, col, scl + 0, sft + 0, agg, cnt);

    // node layer 1: o1 = concat(x, agg/cnt) @ w2a        (+stats slot 2)
    gemm_f16<2><<<(NN + 127) / 128, 256, GEMM_SMEM>>>(x, agg, nullptr, nullptr, nullptr,
                                 cnt, nullptr, nullptr, nullptr, nullptr, 0.f,
                                 wt + WT_W2A, o1, nullptr, NN, sum + 256, sumsq + 256);

    // node layer 2: o2 = relu(bn2a(o1)) @ w2b            (+stats slot 3)
    gemm_f16<1><<<(NN + 127) / 128, 256, GEMM_SMEM>>>(nullptr, nullptr, o1, nullptr, nullptr,
                                 nullptr, sum + 256, sumsq + 256, g2a, be2a, 1.0f / NN,
                                 wt + WT_W2B, o2, nullptr, NN, sum + 384, sumsq + 384);

    // fold bn2b stats once, then output (warp per node): o + attn
    bnfold_kernel<<<1, 128>>>(sum + 384, sumsq + 384, g2b, be2b, 1.0f / NN,
                              scl + 128, sft + 128);
    output_kernel<<<NN / 8, 256>>>(o2, scl + 128, sft + 128, wa, ba, out);
}

// round 15
// speedup vs baseline: 1.0038x; 1.0038x over previous
#include <cuda_runtime.h>
#include <cuda_fp16.h>
#include <cstdint>
#include <cmath>

// Problem constants (fixed by the dataset)
#define EE 800000
#define NN 50000
#define BN_EPS 1e-5f
#define NTILES_E (EE / 128)      // 6250
#define EDGE_GRID 296

// ---------------------------------------------------------------------------
// Scratch (device globals; no runtime allocation)
// ---------------------------------------------------------------------------
__device__ __align__(16) __half g_h1[(size_t)EE * 128];
__device__ __align__(16) __half g_h2[(size_t)EE * 128];
__device__ __align__(16) __half g_o1[(size_t)NN * 128];
__device__ __align__(16) __half g_o2[(size_t)NN * 128];
__device__ __align__(16) float  g_xw[(size_t)NN * 128];   // x @ w1a[128:256]
__device__ __align__(16) float g_agg[(size_t)NN * 128];
__device__ int   g_cnt[NN];
__device__ float g_sum  [512];                  // 4 layers x 128 col sums
__device__ float g_sumsq[512];                  // 4 layers x 128 col sumsq
__device__ __align__(16) __half g_wt16[98304];  // transposed fp16 weights

// weight slice offsets inside g_wt16 (all [n][k] K-major rows)
#define WT_LO  0        // w1a rows   0..127  (K=128)
#define WT_HI  16384    // w1a rows 128..255  (K=128)
#define WT_W1B 32768    // w1b                (K=128)
#define WT_W2A 49152    // w2a                (K=256)
#define WT_W2B 81920    // w2b                (K=128)

// ---------------------------------------------------------------------------
// Helpers
// ---------------------------------------------------------------------------
__device__ __forceinline__ uint32_t packh2(float a, float b) {
    __half2 h = __floats2half2_rn(a, b);
    return *(uint32_t*)&h;
}

__device__ __forceinline__ uint32_t smem_u32(const void* p) {
    return (uint32_t)__cvta_generic_to_shared(p);
}

__device__ __forceinline__ void cp_async16(uint32_t dst, const void* src) {
    asm volatile("cp.async.cg.shared.global [%0], [%1], 16;"
                 :: "r"(dst), "l"(src));
}
__device__ __forceinline__ void cp_commit() {
    asm volatile("cp.async.commit_group;" ::: "memory");
}
__device__ __forceinline__ void cp_wait0() {
    asm volatile("cp.async.wait_group 0;" ::: "memory");
}

__device__ __forceinline__ void red_add_v4(float* p, float4 v) {
    asm volatile("red.global.add.v4.f32 [%0], {%1,%2,%3,%4};"
                 :: "l"(p), "f"(v.x), "f"(v.y), "f"(v.z), "f"(v.w) : "memory");
}

// ldmatrix: four 8x8 b16 matrices (non-transposed)
__device__ __forceinline__ void ldsm_x4(uint32_t& r0, uint32_t& r1,
                                        uint32_t& r2, uint32_t& r3,
                                        uint32_t addr) {
    asm volatile("ldmatrix.sync.aligned.m8n8.x4.shared.b16 {%0,%1,%2,%3}, [%4];"
                 : "=r"(r0), "=r"(r1), "=r"(r2), "=r"(r3) : "r"(addr));
}

// mma.m16n8k16 fp16 in, fp32 accumulate
__device__ __forceinline__ void mma_f16(float* c, const uint32_t* a,
                                        uint32_t b0, uint32_t b1) {
    asm volatile(
        "mma.sync.aligned.m16n8k16.row.col.f32.f16.f16.f32 "
        "{%0,%1,%2,%3}, {%4,%5,%6,%7}, {%8,%9}, {%0,%1,%2,%3};"
        : "+f"(c[0]), "+f"(c[1]), "+f"(c[2]), "+f"(c[3])
        : "r"(a[0]), "r"(a[1]), "r"(a[2]), "r"(a[3]), "r"(b0), "r"(b1));
}

__device__ __forceinline__ void sts_v4(uint32_t dst, uint4 o) {
    asm volatile("st.shared.v4.b32 [%0], {%1,%2,%3,%4};"
                 :: "r"(dst), "r"(o.x), "r"(o.y), "r"(o.z), "r"(o.w));
}

__device__ __forceinline__ uint32_t h2_affine_relu(uint32_t a, uint32_t s,
                                                   uint32_t f, __half2 z2) {
    __half2 r = __hfma2(*(__half2*)&a, *(__half2*)&s, *(__half2*)&f);
    r = __hmax2(r, z2);
    return *(uint32_t*)&r;
}

// per-lane inline BN fold for 4 consecutive features (f32, same expression
// as always: m = sum/M; v = max(sq/M - m*m, 0); sc = g*rsqrt(v+eps);
// sf = b - m*sc). Loads hit L2 (psum/psq just written by GEMM atomics).
__device__ __forceinline__ void fold4(const float* __restrict__ psum,
                                      const float* __restrict__ psq,
                                      const float* __restrict__ gamma,
                                      const float* __restrict__ beta,
                                      float invM, int c0,
                                      float4& sc, float4& sf)
{
    float4 s = __ldg((const float4*)(psum  + c0));
    float4 q = __ldg((const float4*)(psq   + c0));
    float4 gm = __ldg((const float4*)(gamma + c0));
    float4 bt = __ldg((const float4*)(beta  + c0));
    float m, v;
    m = s.x * invM; v = fmaxf(q.x * invM - m * m, 0.f);
    sc.x = gm.x * rsqrtf(v + BN_EPS); sf.x = bt.x - m * sc.x;
    m = s.y * invM; v = fmaxf(q.y * invM - m * m, 0.f);
    sc.y = gm.y * rsqrtf(v + BN_EPS); sf.y = bt.y - m * sc.y;
    m = s.z * invM; v = fmaxf(q.z * invM - m * m, 0.f);
    sc.z = gm.z * rsqrtf(v + BN_EPS); sf.z = bt.z - m * sc.z;
    m = s.w * invM; v = fmaxf(q.w * invM - m * m, 0.f);
    sc.w = gm.w * rsqrtf(v + BN_EPS); sf.w = bt.w - m * sc.w;
}

// ---------------------------------------------------------------------------
// prep: zero accumulators (vectorized) + transpose/convert weights to f16
// ---------------------------------------------------------------------------
__global__ void prep_kernel(float4* __restrict__ agg4, int* __restrict__ cnt,
                            float* __restrict__ sum, float* __restrict__ sumsq,
                            __half* __restrict__ wt,
                            const float* __restrict__ w1a, const float* __restrict__ w1b,
                            const float* __restrict__ w2a, const float* __restrict__ w2b)
{
    int idx = blockIdx.x * blockDim.x + threadIdx.x;
    if (idx < NN * 32) agg4[idx] = make_float4(0.f, 0.f, 0.f, 0.f);
    if (idx < NN)      cnt[idx] = 0;
    if (idx < 512) { sum[idx] = 0.f; sumsq[idx] = 0.f; }
    if (idx < 98304) {
        float v;
        if (idx < 16384) {                        // w1a lo: k 0..127
            int n = idx >> 7, k = idx & 127;
            v = w1a[k * 128 + n];
        } else if (idx < 32768) {                 // w1a hi: k 128..255
            int i = idx - 16384, n = i >> 7, k = i & 127;
            v = w1a[(128 + k) * 128 + n];
        } else if (idx < 49152) {                 // w1b
            int i = idx - 32768, n = i >> 7, k = i & 127;
            v = w1b[k * 128 + n];
        } else if (idx < 81920) {                 // w2a: K=256
            int i = idx - 49152, n = i >> 8, k = i & 255;
            v = w2a[k * 128 + n];
        } else {                                  // w2b
            int i = idx - 81920, n = i >> 7, k = i & 127;
            v = w2b[k * 128 + n];
        }
        wt[idx] = __float2half_rn(v);
    }
}

// ---------------------------------------------------------------------------
// Shared compute core for persistent edge kernel (K=128, 256B smem rows).
// BN=true applies in-fragment affine+relu using half2 scale/shift tables.
// ---------------------------------------------------------------------------
template<bool BN>
__device__ __forceinline__ void compute_steps(
    uint32_t aB, uint32_t bB, float acc[2][8][4],
    const int* rA, const int* rB, int uHi, int t4,
    const __half2* sScl2, const __half2* sSft2, __half2 z2)
{
#pragma unroll
    for (int step = 0; step < 8; step++) {
        const int unit = step * 2 + uHi;
        uint32_t a[2][4];
#pragma unroll
        for (int mi = 0; mi < 2; mi++)
            ldsm_x4(a[mi][0], a[mi][1], a[mi][2], a[mi][3],
                    aB + (uint32_t)(rA[mi] * 256 + ((unit ^ (rA[mi] & 7)) << 4)));
        if (BN) {
            int b = step * 8 + t4;
            uint32_t cl = *(const uint32_t*)(sScl2 + b);
            uint32_t fl = *(const uint32_t*)(sSft2 + b);
            uint32_t ch = *(const uint32_t*)(sScl2 + b + 4);
            uint32_t fh = *(const uint32_t*)(sSft2 + b + 4);
#pragma unroll
            for (int mi = 0; mi < 2; mi++) {
                a[mi][0] = h2_affine_relu(a[mi][0], cl, fl, z2);
                a[mi][1] = h2_affine_relu(a[mi][1], cl, fl, z2);
                a[mi][2] = h2_affine_relu(a[mi][2], ch, fh, z2);
                a[mi][3] = h2_affine_relu(a[mi][3], ch, fh, z2);
            }
        }
#pragma unroll
        for (int p = 0; p < 4; p++) {
            uint32_t b0, b1, b2, b3;
            ldsm_x4(b0, b1, b2, b3,
                    bB + (uint32_t)(rB[p] * 256 + ((unit ^ (rB[p] & 7)) << 4)));
#pragma unroll
            for (int mi = 0; mi < 2; mi++) {
                mma_f16(acc[mi][2 * p],     a[mi], b0, b2);
                mma_f16(acc[mi][2 * p + 1], a[mi], b1, b3);
            }
        }
    }
}

// stats shuffle-reduce + smem atomics (padless tiles)
__device__ __forceinline__ void stats_reduce(
    float acc[2][8][4], int lane, int t4, int wcc,
    float* sSum, float* sSq)
{
#pragma unroll
    for (int ni = 0; ni < 8; ni++) {
        float s0 = 0, q0 = 0, s1 = 0, q1 = 0;
#pragma unroll
        for (int mi = 0; mi < 2; mi++) {
            float a0 = acc[mi][ni][0], a2 = acc[mi][ni][2];
            float a1 = acc[mi][ni][1], a3 = acc[mi][ni][3];
            s0 += a0 + a2; q0 += a0 * a0 + a2 * a2;
            s1 += a1 + a3; q1 += a1 * a1 + a3 * a3;
        }
#pragma unroll
        for (int off = 4; off < 32; off <<= 1) {
            s0 += __shfl_xor_sync(0xFFFFFFFFu, s0, off);
            q0 += __shfl_xor_sync(0xFFFFFFFFu, q0, off);
            s1 += __shfl_xor_sync(0xFFFFFFFFu, s1, off);
            q1 += __shfl_xor_sync(0xFFFFFFFFu, q1, off);
        }
        if (lane < 4) {
            int c0 = wcc + ni * 8 + 2 * t4;
            atomicAdd(&sSum[c0],     s0); atomicAdd(&sSq[c0],     q0);
            atomicAdd(&sSum[c0 + 1], s1); atomicAdd(&sSq[c0 + 1], q1);
        }
    }
}

// epilogue: acc -> f16 smem staging (256B rows, swizzled) -> coalesced STG
__device__ __forceinline__ void epi_store(
    char* epi, __half* Hout, int bm, int tid, int g, int t4,
    int wr, int wcc, float acc[2][8][4])
{
#pragma unroll
    for (int mi = 0; mi < 2; mi++) {
        int r0 = wr + mi * 16 + g;
        int r1 = r0 + 8;
#pragma unroll
        for (int ni = 0; ni < 8; ni++) {
            int col = wcc + ni * 8 + 2 * t4;
            *(uint32_t*)(epi + r0 * 256 + ((col * 2) ^ ((r0 & 7) << 5))) =
                packh2(acc[mi][ni][0], acc[mi][ni][1]);
            *(uint32_t*)(epi + r1 * 256 + ((col * 2) ^ ((r1 & 7) << 5))) =
                packh2(acc[mi][ni][2], acc[mi][ni][3]);
        }
    }
    __syncthreads();
#pragma unroll
    for (int i = 0; i < 8; i++) {
        int gid = tid + i * 256;
        int row = gid >> 4;
        int seg = gid & 15;
        uint4 v = *(uint4*)(epi + row * 256 + ((seg * 16) ^ ((row & 7) << 5)));
        *(uint4*)(Hout + (size_t)(bm + row) * 128 + seg * 8) = v;
    }
}

// ---------------------------------------------------------------------------
// Persistent edge GEMM 2 (M=128 tiles, round-10 proven): h2 = relu(bn(h1))@w1b
// A via cp.async (f16), BN+relu in-fragment. smem: A0|A1|B (96KB), 2 CTA/SM.
// ---------------------------------------------------------------------------
__launch_bounds__(256, 2)
__global__ void gemm_edge2(
    const __half* __restrict__ h1,
    const float*  __restrict__ psum, const float* __restrict__ psq,
    const float*  __restrict__ gamma, const float* __restrict__ beta,
    const __half* __restrict__ Wt,     // WT_W1B slice
    __half* __restrict__ Hout,
    float* __restrict__ osum, float* __restrict__ osq)
{
    extern __shared__ char dyns[];
    const uint32_t raw   = smem_u32(dyns);
    const uint32_t sbase = (raw + 1023u) & ~1023u;
    char* gbase = dyns + (sbase - raw);
    const uint32_t bB = sbase + 65536u;

    __shared__ __half2 sScl2[64], sSft2[64];
    __shared__ float sSum[128], sSq[128];

    const int tid  = threadIdx.x;
    const int warp = tid >> 5;
    const int lane = tid & 31;
    const int g    = lane >> 2;
    const int t4   = lane & 3;
    const int wr   = (warp & 3) * 32;
    const int wcc  = (warp >> 2) * 64;
    const int uHi  = (lane >> 4);

    if (tid < 128) { sSum[tid] = 0.f; sSq[tid] = 0.f; }
    if (tid < 64) {
        const float invM = 1.0f / EE;
        int k0 = 2 * tid, k1 = k0 + 1;
        float m0 = psum[k0] * invM;
        float v0 = fmaxf(psq[k0] * invM - m0 * m0, 0.f);
        float s0 = gamma[k0] * rsqrtf(v0 + BN_EPS);
        float f0 = beta[k0] - m0 * s0;
        float m1 = psum[k1] * invM;
        float v1 = fmaxf(psq[k1] * invM - m1 * m1, 0.f);
        float s1 = gamma[k1] * rsqrtf(v1 + BN_EPS);
        float f1 = beta[k1] - m1 * s1;
        sScl2[tid] = __floats2half2_rn(s0, s1);
        sSft2[tid] = __floats2half2_rn(f0, f1);
    }

    int rA[2], rB[4];
#pragma unroll
    for (int mi = 0; mi < 2; mi++)
        rA[mi] = wr + mi * 16 + (lane & 7) + ((lane >> 3) & 1) * 8;
#pragma unroll
    for (int p = 0; p < 4; p++)
        rB[p] = wcc + p * 16 + (lane & 7) + ((lane >> 3) & 1) * 8;

    auto cpA = [&](int t, int s) {
        const uint32_t aB = sbase + (uint32_t)s * 32768u;
#pragma unroll
        for (int j = 0; j < 8; j++) {
            int u = tid + j * 256, row = u >> 4, unit = u & 15;
            cp_async16(aB + (uint32_t)(row * 256 + ((unit ^ (row & 7)) << 4)),
                       h1 + (size_t)(t * 128 + row) * 128 + unit * 8);
        }
        cp_commit();
    };

    // prologue: B + A(t0) in one group
#pragma unroll
    for (int j = 0; j < 8; j++) {
        int u = tid + j * 256, n = u >> 4, unit = u & 15;
        cp_async16(bB + (uint32_t)(n * 256 + ((unit ^ (n & 7)) << 4)),
                   Wt + (size_t)n * 128 + unit * 8);
    }
    int t0 = blockIdx.x;
    if (t0 < NTILES_E) {
#pragma unroll
        for (int j = 0; j < 8; j++) {
            int u = tid + j * 256, row = u >> 4, unit = u & 15;
            cp_async16(sbase + (uint32_t)(row * 256 + ((unit ^ (row & 7)) << 4)),
                       h1 + (size_t)(t0 * 128 + row) * 128 + unit * 8);
        }
    }
    cp_commit();

    const __half2 z2 = __floats2half2_rn(0.f, 0.f);
    int i = 0;
    for (int t = t0; t < NTILES_E; t += gridDim.x, i++) {
        const int s  = i & 1;
        const uint32_t aB = sbase + (uint32_t)s * 32768u;
        char* epi = gbase + s * 32768;

        cp_wait0();
        __syncthreads();                              // A(t) (+B first) visible

        int tn = t + gridDim.x;
        if (tn < NTILES_E) cpA(tn, s ^ 1);

        float acc[2][8][4];
#pragma unroll
        for (int mi = 0; mi < 2; mi++)
#pragma unroll
            for (int ni = 0; ni < 8; ni++)
#pragma unroll
                for (int v = 0; v < 4; v++) acc[mi][ni][v] = 0.0f;

        compute_steps<true>(aB, bB, acc, rA, rB, uHi, t4, sScl2, sSft2, z2);
        stats_reduce(acc, lane, t4, wcc, sSum, sSq);
        __syncthreads();                              // A_s reads done
        epi_store(epi, Hout, t * 128, tid, g, t4, wr, wcc, acc);
    }

    __syncthreads();
    if (tid < 128) {
        atomicAdd(osum + tid, sSum[tid]);
        atomicAdd(osq  + tid, sSq[tid]);
    }
}

// ---------------------------------------------------------------------------
// Tiled GEMM (round-8 proven): out[M,128] = A[M,K] @ W[K,128] + fused stats.
// MODE 0: A = message (K=128); epilogue acc += xw[row[r]] BEFORE stats
// MODE 1: A = relu(prev*scale + shift)     (K=128, f16 source)
// MODE 2: A = concat(x, agg_sum*inv_cnt)   (K=256, f32 sources)
// MODE 3: A = x (K=128, f32); plain gemm, f32 out, no stats (xw precompute)
// ---------------------------------------------------------------------------
template<int MODE>
__launch_bounds__(256, 2)
__global__ void gemm_f16(
    const float*  __restrict__ A0f,
    const float*  __restrict__ A1f,
    const __half* __restrict__ A0h,
    const float*  __restrict__ xw,
    const int*    __restrict__ ridx,
    const int*    __restrict__ cnt,
    const float*  __restrict__ psum,
    const float*  __restrict__ psq,
    const float*  __restrict__ gamma,
    const float*  __restrict__ beta,
    float         invPrevM,
    const __half* __restrict__ Wt,
    __half* __restrict__ Hout,
    float*  __restrict__ Hout32,
    int M,
    float* __restrict__ osum,
    float* __restrict__ osq)
{
    constexpr int K   = (MODE == 2) ? 256 : 128;
    constexpr int NIT = K / 64;

    extern __shared__ char dyns[];
    const uint32_t raw   = smem_u32(dyns);
    const uint32_t sbase = (raw + 1023u) & ~1023u;
    char* gbase = dyns + (sbase - raw);

    __shared__ int   sRow[128];
    __shared__ float sInv[128], sScl[128], sSft[128];
    __shared__ float sSum[128], sSq[128];

    const int tid  = threadIdx.x;
    const int warp = tid >> 5;
    const int lane = tid & 31;
    const int bm   = blockIdx.x * 128;

    if (tid < 128) { sSum[tid] = 0.f; sSq[tid] = 0.f; }
    if (MODE == 0 && tid < 128) sRow[tid] = ridx[bm + tid];
    if (MODE == 2 && tid < 128) {
        int r = bm + tid;
        int c = (r < M) ? cnt[r] : 1;
        sInv[tid] = 1.0f / (float)(c > 1 ? c : 1);
    }
    if (MODE == 1 && tid < 128) {
        float m  = psum[tid] * invPrevM;
        float v  = fmaxf(psq[tid] * invPrevM - m * m, 0.f);
        float sc = gamma[tid] * rsqrtf(v + BN_EPS);
        sScl[tid] = sc;
        sSft[tid] = beta[tid] - m * sc;
    }
    __syncthreads();

    auto ldgA = [&](int it, float4* pf, uint4* ph) {
        const int k0 = it * 64;
#pragma unroll
        for (int j = 0; j < 4; j++) {
            int u = tid + j * 256, row = u >> 3, unit = u & 7;
            int kg = k0 + unit * 8;
            int rg = bm + row;
            if (MODE == 1) {
                ph[j] = (rg < M) ? *(const uint4*)(A0h + (size_t)rg * 128 + kg)
                                 : make_uint4(0, 0, 0, 0);
            } else if (MODE == 0) {
                const float* src = A0f + (size_t)rg * 128 + kg;  // EE % 128 == 0
                pf[2 * j]     = *(const float4*)src;
                pf[2 * j + 1] = *(const float4*)(src + 4);
            } else {
                if (rg < M) {
                    const float* src = (MODE == 3 || kg < 128)
                        ? (A0f + (size_t)rg * 128 + kg)
                        : (A1f + (size_t)rg * 128 + (kg - 128));
                    pf[2 * j]     = *(const float4*)src;
                    pf[2 * j + 1] = *(const float4*)(src + 4);
                } else {
                    pf[2 * j]     = make_float4(0, 0, 0, 0);
                    pf[2 * j + 1] = make_float4(0, 0, 0, 0);
                }
            }
        }
    };

    auto stsA = [&](int it, int s, const float4* pf, const uint4* ph) {
        const int k0 = it * 64;
        const uint32_t aB = sbase + (uint32_t)s * 16384u;
#pragma unroll
        for (int j = 0; j < 4; j++) {
            int u = tid + j * 256, row = u >> 3, unit = u & 7;
            int kg = k0 + unit * 8;
            int rg = bm + row;
            uint32_t dst = aB + (uint32_t)(row * 128 + ((unit ^ (row & 7)) << 4));
            uint4 o;
            if (MODE == 0) {
                float4 p = pf[2 * j], q = pf[2 * j + 1];
                o.x = packh2(p.x, p.y); o.y = packh2(p.z, p.w);
                o.z = packh2(q.x, q.y); o.w = packh2(q.z, q.w);
            } else if (MODE == 1) {
                if (rg < M) {
                    uint4 rv = ph[j];
                    float4 sc0 = *(const float4*)(sScl + kg);
                    float4 sc1 = *(const float4*)(sScl + kg + 4);
                    float4 sf0 = *(const float4*)(sSft + kg);
                    float4 sf1 = *(const float4*)(sSft + kg + 4);
                    float2 v0 = __half22float2(*(__half2*)&rv.x);
                    float2 v1 = __half22float2(*(__half2*)&rv.y);
                    float2 v2 = __half22float2(*(__half2*)&rv.z);
                    float2 v3 = __half22float2(*(__half2*)&rv.w);
                    o.x = packh2(fmaxf(fmaf(v0.x, sc0.x, sf0.x), 0.f),
                                 fmaxf(fmaf(v0.y, sc0.y, sf0.y), 0.f));
                    o.y = packh2(fmaxf(fmaf(v1.x, sc0.z, sf0.z), 0.f),
                                 fmaxf(fmaf(v1.y, sc0.w, sf0.w), 0.f));
                    o.z = packh2(fmaxf(fmaf(v2.x, sc1.x, sf1.x), 0.f),
                                 fmaxf(fmaf(v2.y, sc1.y, sf1.y), 0.f));
                    o.w = packh2(fmaxf(fmaf(v3.x, sc1.z, sf1.z), 0.f),
                                 fmaxf(fmaf(v3.y, sc1.w, sf1.w), 0.f));
                } else {
                    o = make_uint4(0, 0, 0, 0);
                }
            } else {
                if (rg < M) {
                    float4 p = pf[2 * j], q = pf[2 * j + 1];
                    if (MODE == 2 && kg >= 128) {
                        float iv = sInv[row];
                        p.x *= iv; p.y *= iv; p.z *= iv; p.w *= iv;
                        q.x *= iv; q.y *= iv; q.z *= iv; q.w *= iv;
                    }
                    o.x = packh2(p.x, p.y); o.y = packh2(p.z, p.w);
                    o.z = packh2(q.x, q.y); o.w = packh2(q.z, q.w);
                } else {
                    o = make_uint4(0, 0, 0, 0);
                }
            }
            sts_v4(dst, o);
        }
    };

    auto cpB = [&](int it, int s) {
        const int k0 = it * 64;
        const uint32_t bB = sbase + 32768u + (uint32_t)s * 16384u;
#pragma unroll
        for (int j = 0; j < 4; j++) {
            int u = tid + j * 256, n = u >> 3, unit = u & 7;
            uint32_t dst = bB + (uint32_t)(n * 128 + ((unit ^ (n & 7)) << 4));
            cp_async16(dst, Wt + (size_t)n * K + k0 + unit * 8);
        }
        cp_commit();
    };

    float acc[2][8][4];
#pragma unroll
    for (int mi = 0; mi < 2; mi++)
#pragma unroll
        for (int ni = 0; ni < 8; ni++)
#pragma unroll
            for (int v = 0; v < 4; v++) acc[mi][ni][v] = 0.0f;

    const int g   = lane >> 2;
    const int t4  = lane & 3;
    const int wm  = warp & 3;
    const int wn  = warp >> 2;
    const int wr  = wm * 32;
    const int wcc = wn * 64;

    int rA[2], rB[4];
#pragma unroll
    for (int mi = 0; mi < 2; mi++)
        rA[mi] = wr + mi * 16 + (lane & 7) + ((lane >> 3) & 1) * 8;
#pragma unroll
    for (int p = 0; p < 4; p++)
        rB[p] = wcc + p * 16 + (lane & 7) + ((lane >> 3) & 1) * 8;
    const int uHi = (lane >> 4);

    {
        float4 pf[8]; uint4 ph[4];
        ldgA(0, pf, ph);
        stsA(0, 0, pf, ph);
        cpB(0, 0);
    }

#pragma unroll 1
    for (int it = 0; it < NIT; it++) {
        const int s = it & 1;
        cp_wait0();
        __syncthreads();

        float4 pf[8]; uint4 ph[4];
        const bool more = (it + 1 < NIT);
        if (more) {
            ldgA(it + 1, pf, ph);
            cpB(it + 1, s ^ 1);
        }

        const uint32_t aB = sbase + (uint32_t)s * 16384u;
        const uint32_t bB = sbase + 32768u + (uint32_t)s * 16384u;

#pragma unroll
        for (int step = 0; step < 4; step++) {
            const int unit = step * 2 + uHi;
            uint32_t a[2][4];
#pragma unroll
            for (int mi = 0; mi < 2; mi++)
                ldsm_x4(a[mi][0], a[mi][1], a[mi][2], a[mi][3],
                        aB + (uint32_t)(rA[mi] * 128 + ((unit ^ (rA[mi] & 7)) << 4)));
#pragma unroll
            for (int p = 0; p < 4; p++) {
                uint32_t b0, b1, b2, b3;
                ldsm_x4(b0, b1, b2, b3,
                        bB + (uint32_t)(rB[p] * 128 + ((unit ^ (rB[p] & 7)) << 4)));
#pragma unroll
                for (int mi = 0; mi < 2; mi++) {
                    mma_f16(acc[mi][2 * p],     a[mi], b0, b2);
                    mma_f16(acc[mi][2 * p + 1], a[mi], b1, b3);
                }
            }
        }

        if (more) stsA(it + 1, s ^ 1, pf, ph);
    }

    // ---- MODE 0: add per-node xw contribution BEFORE stats ----
    if (MODE == 0) {
#pragma unroll
        for (int mi = 0; mi < 2; mi++) {
            const float* x0 = xw + (size_t)sRow[wr + mi * 16 + g]     * 128;
            const float* x1 = xw + (size_t)sRow[wr + mi * 16 + g + 8] * 128;
#pragma unroll
            for (int ni = 0; ni < 8; ni++) {
                int col = wcc + ni * 8 + 2 * t4;
                float2 u0 = *(const float2*)(x0 + col);
                float2 u1 = *(const float2*)(x1 + col);
                acc[mi][ni][0] += u0.x; acc[mi][ni][1] += u0.y;
                acc[mi][ni][2] += u1.x; acc[mi][ni][3] += u1.y;
            }
        }
    }

    if (MODE != 3) {
#pragma unroll
        for (int ni = 0; ni < 8; ni++) {
            float s0 = 0, q0 = 0, s1 = 0, q1 = 0;
#pragma unroll
            for (int mi = 0; mi < 2; mi++) {
                float a0 = acc[mi][ni][0], a2 = acc[mi][ni][2];
                float a1 = acc[mi][ni][1], a3 = acc[mi][ni][3];
                s0 += a0 + a2; q0 += a0 * a0 + a2 * a2;
                s1 += a1 + a3; q1 += a1 * a1 + a3 * a3;
            }
#pragma unroll
            for (int off = 4; off < 32; off <<= 1) {
                s0 += __shfl_xor_sync(0xFFFFFFFFu, s0, off);
                q0 += __shfl_xor_sync(0xFFFFFFFFu, q0, off);
                s1 += __shfl_xor_sync(0xFFFFFFFFu, s1, off);
                q1 += __shfl_xor_sync(0xFFFFFFFFu, q1, off);
            }
            if (lane < 4) {
                int c0 = wcc + ni * 8 + 2 * t4;
                atomicAdd(&sSum[c0],     s0); atomicAdd(&sSq[c0],     q0);
                atomicAdd(&sSum[c0 + 1], s1); atomicAdd(&sSq[c0 + 1], q1);
            }
        }
    }

    __syncthreads();
    char* epi = gbase;

    if (MODE == 3) {
#pragma unroll
        for (int mi = 0; mi < 2; mi++) {
            int r0 = wr + mi * 16 + g;
            int r1 = r0 + 8;
#pragma unroll
            for (int ni = 0; ni < 8; ni++) {
                int col = wcc + ni * 8 + 2 * t4;
                *(float2*)(epi + r0 * 512 + ((col * 4) ^ ((r0 & 7) << 5))) =
                    make_float2(acc[mi][ni][0], acc[mi][ni][1]);
                *(float2*)(epi + r1 * 512 + ((col * 4) ^ ((r1 & 7) << 5))) =
                    make_float2(acc[mi][ni][2], acc[mi][ni][3]);
            }
        }
        __syncthreads();
#pragma unroll
        for (int i = 0; i < 16; i++) {
            int gid = tid + i * 256;
            int row = gid >> 5;
            int seg = gid & 31;
            if (bm + row < M) {
                uint4 v = *(uint4*)(epi + row * 512 + ((seg * 16) ^ ((row & 7) << 5)));
                *(uint4*)(Hout32 + (size_t)(bm + row) * 128 + seg * 4) = v;
            }
        }
        return;
    }

#pragma unroll
    for (int mi = 0; mi < 2; mi++) {
        int r0 = wr + mi * 16 + g;
        int r1 = r0 + 8;
#pragma unroll
        for (int ni = 0; ni < 8; ni++) {
            int col = wcc + ni * 8 + 2 * t4;
            *(uint32_t*)(epi + r0 * 256 + ((col * 2) ^ ((r0 & 7) << 5))) =
                packh2(acc[mi][ni][0], acc[mi][ni][1]);
            *(uint32_t*)(epi + r1 * 256 + ((col * 2) ^ ((r1 & 7) << 5))) =
                packh2(acc[mi][ni][2], acc[mi][ni][3]);
        }
    }
    __syncthreads();
#pragma unroll
    for (int i = 0; i < 8; i++) {
        int gid = tid + i * 256;
        int row = gid >> 4;
        int seg = gid & 15;
        if (bm + row < M) {
            uint4 v = *(uint4*)(epi + row * 256 + ((seg * 16) ^ ((row & 7) << 5)));
            *(uint4*)(Hout + (size_t)(bm + row) * 128 + seg * 8) = v;
        }
    }

    if (tid < 128) {
        atomicAdd(osum + tid, sSum[tid]);
        atomicAdd(osq  + tid, sSq[tid]);
    }
}

// ---------------------------------------------------------------------------
// Scatter: agg[col[e]] += relu(bn(h2_f16[e])), cnt[col[e]] += 1
// 8 edges per warp, 64 edges per block (round-10 proven shape);
// BN fold computed inline per lane (4 features) — no bnfold kernel needed.
// ---------------------------------------------------------------------------
__global__ void scatter_kernel(const __half* __restrict__ h2,
                               const int* __restrict__ col,
                               const float* __restrict__ psum,
                               const float* __restrict__ psq,
                               const float* __restrict__ gamma,
                               const float* __restrict__ beta,
                               float* __restrict__ agg, int* __restrict__ cnt)
{
    const int t    = threadIdx.x;        // 256
    const int warp = t >> 5;
    const int lane = t & 31;

    float4 sc, sf;
    fold4(psum, psq, gamma, beta, 1.0f / EE, lane * 4, sc, sf);

    const int e0 = blockIdx.x * 64 + warp * 8;
#pragma unroll
    for (int i = 0; i < 8; i++) {
        int e = e0 + i;
        int c = __ldg(col + e);
        uint2 rawv = *(const uint2*)(h2 + (size_t)e * 128 + lane * 4);
        float2 a = __half22float2(*(__half2*)&rawv.x);
        float2 b = __half22float2(*(__half2*)&rawv.y);
        float4 v;
        v.x = fmaxf(fmaf(a.x, sc.x, sf.x), 0.f);
        v.y = fmaxf(fmaf(a.y, sc.y, sf.y), 0.f);
        v.z = fmaxf(fmaf(b.x, sc.z, sf.z), 0.f);
        v.w = fmaxf(fmaf(b.y, sc.w, sf.w), 0.f);
        red_add_v4(agg + (size_t)c * 128 + lane * 4, v);
        if (lane == 0) atomicAdd(cnt + c, 1);
    }
}

// ---------------------------------------------------------------------------
// Final: o = relu(bn(o2)); attn = sigmoid(o @ wa + ba)
// One warp per node (8 nodes/block); BN fold computed inline per lane.
// ---------------------------------------------------------------------------
__global__ void output_kernel(const __half* __restrict__ o2,
                              const float* __restrict__ psum,
                              const float* __restrict__ psq,
                              const float* __restrict__ gamma,
                              const float* __restrict__ beta,
                              const float* __restrict__ wa,
                              const float* __restrict__ ba,
                              float* __restrict__ out)
{
    const int warp = threadIdx.x >> 5;
    const int lane = threadIdx.x & 31;
    const int n    = blockIdx.x * 8 + warp;   // NN % 8 == 0

    float4 sc, sf;
    fold4(psum, psq, gamma, beta, 1.0f / NN, lane * 4, sc, sf);
    const float4 w = __ldg((const float4*)(wa + lane * 4));

    uint2 rawv = *(const uint2*)(o2 + (size_t)n * 128 + lane * 4);
    float2 a = __half22float2(*(__half2*)&rawv.x);
    float2 b = __half22float2(*(__half2*)&rawv.y);
    float4 v;
    v.x = fmaxf(fmaf(a.x, sc.x, sf.x), 0.f);
    v.y = fmaxf(fmaf(a.y, sc.y, sf.y), 0.f);
    v.z = fmaxf(fmaf(b.x, sc.z, sf.z), 0.f);
    v.w = fmaxf(fmaf(b.y, sc.w, sf.w), 0.f);
    *(float4*)(out + (size_t)n * 128 + lane * 4) = v;

    float p = v.x * w.x + v.y * w.y + v.z * w.z + v.w * w.w;
#pragma unroll
    for (int off = 16; off > 0; off >>= 1)
        p += __shfl_xor_sync(0xFFFFFFFFu, p, off);
    if (lane == 0)
        out[(size_t)NN * 128 + n] = 1.0f / (1.0f + expf(-(p + __ldg(ba))));
}

// ---------------------------------------------------------------------------
// Launch
// ---------------------------------------------------------------------------
#define GEMM_SMEM (65536 + 1024)
#define EDGE_SMEM (98304 + 1024)

extern "C" void kernel_launch(void* const* d_in, const int* in_sizes, int n_in,
                              void* d_out, int out_size)
{
    const float* x       = (const float*)d_in[0];
    const int*   ei      = (const int*)  d_in[1];   // [2,E]: row then col
    const float* message = (const float*)d_in[2];
    const float* w1a  = (const float*)d_in[3];
    const float* g1a  = (const float*)d_in[5];
    const float* be1a = (const float*)d_in[6];
    const float* w1b  = (const float*)d_in[7];
    const float* g1b  = (const float*)d_in[9];
    const float* be1b = (const float*)d_in[10];
    const float* w2a  = (const float*)d_in[11];
    const float* g2a  = (const float*)d_in[13];
    const float* be2a = (const float*)d_in[14];
    const float* w2b  = (const float*)d_in[15];
    const float* g2b  = (const float*)d_in[17];
    const float* be2b = (const float*)d_in[18];
    const float* wa   = (const float*)d_in[19];
    const float* ba   = (const float*)d_in[20];
    float* out = (float*)d_out;

    __half *h1, *h2, *o1, *o2, *wt;
    float *agg, *sum, *sumsq, *xw;
    int* cnt;
    cudaGetSymbolAddress((void**)&h1,    g_h1);
    cudaGetSymbolAddress((void**)&h2,    g_h2);
    cudaGetSymbolAddress((void**)&o1,    g_o1);
    cudaGetSymbolAddress((void**)&o2,    g_o2);
    cudaGetSymbolAddress((void**)&xw,    g_xw);
    cudaGetSymbolAddress((void**)&agg,   g_agg);
    cudaGetSymbolAddress((void**)&cnt,   g_cnt);
    cudaGetSymbolAddress((void**)&sum,   g_sum);
    cudaGetSymbolAddress((void**)&sumsq, g_sumsq);
    cudaGetSymbolAddress((void**)&wt,    g_wt16);

    const int* row = ei;
    const int* col = ei + EE;

    static bool attr_done = false;
    if (!attr_done) {
        cudaFuncSetAttribute(gemm_f16<0>, cudaFuncAttributeMaxDynamicSharedMemorySize, GEMM_SMEM);
        cudaFuncSetAttribute(gemm_f16<1>, cudaFuncAttributeMaxDynamicSharedMemorySize, GEMM_SMEM);
        cudaFuncSetAttribute(gemm_f16<2>, cudaFuncAttributeMaxDynamicSharedMemorySize, GEMM_SMEM);
        cudaFuncSetAttribute(gemm_f16<3>, cudaFuncAttributeMaxDynamicSharedMemorySize, GEMM_SMEM);
        cudaFuncSetAttribute(gemm_edge2, cudaFuncAttributeMaxDynamicSharedMemorySize, EDGE_SMEM);
        attr_done = true;
    }

    prep_kernel<<<(NN * 32 + 1023) / 1024, 1024>>>((float4*)agg, cnt, sum, sumsq,
                                                   wt, w1a, w1b, w2a, w2b);

    // xw = x @ w1a[128:256]  (f32 out, no stats)
    gemm_f16<3><<<(NN + 127) / 128, 256, GEMM_SMEM>>>(x, nullptr, nullptr, nullptr,
                                 nullptr, nullptr, nullptr, nullptr, nullptr, nullptr, 0.f,
                                 wt + WT_HI, nullptr, xw, NN, nullptr, nullptr);

    // edge layer 1 (round-8 proven): h1 = message @ w1a_lo + xw[row]  (+slot 0)
    gemm_f16<0><<<EE / 128, 256, GEMM_SMEM>>>(message, nullptr, nullptr, xw, row,
                                 nullptr, nullptr, nullptr, nullptr, nullptr, 0.f,
                                 wt + WT_LO, h1, nullptr, EE, sum + 0, sumsq + 0);

    // edge layer 2 (persistent M=128, proven): h2 = relu(bn1a(h1)) @ w1b
    gemm_edge2<<<EDGE_GRID, 256, EDGE_SMEM>>>(h1, sum + 0, sumsq + 0, g1a, be1a,
                                              wt + WT_W1B, h2, sum + 128, sumsq + 128);

    // scatter (8 edges/warp, proven shape) with inline bn1b fold
    scatter_kernel<<<EE / 64, 256>>>(h2, col, sum + 128, sumsq + 128, g1b, be1b,
                                     agg, cnt);

    // node layer 1: o1 = concat(x, agg/cnt) @ w2a        (+stats slot 2)
    gemm_f16<2><<<(NN + 127) / 128, 256, GEMM_SMEM>>>(x, agg, nullptr, nullptr, nullptr,
                                 cnt, nullptr, nullptr, nullptr, nullptr, 0.f,
                                 wt + WT_W2A, o1, nullptr, NN, sum + 256, sumsq + 256);

    // node layer 2: o2 = relu(bn2a(o1)) @ w2b            (+stats slot 3)
    gemm_f16<1><<<(NN + 127) / 128, 256, GEMM_SMEM>>>(nullptr, nullptr, o1, nullptr, nullptr,
                                 nullptr, sum + 256, sumsq + 256, g2a, be2a, 1.0f / NN,
                                 wt + WT_W2B, o2, nullptr, NN, sum + 384, sumsq + 384);

    // output (warp per node) with inline bn2b fold: o + attn
    output_kernel<<<NN / 8, 256>>>(o2, sum + 384, sumsq + 384, g2b, be2b,
                                   wa, ba, out);
}

// round 16
// speedup vs baseline: 1.0038x; 1.0001x over previous
#include <cuda_runtime.h>
#include <cuda_fp16.h>
#include <cstdint>
#include <cmath>

// Problem constants (fixed by the dataset)
#define EE 800000
#define NN 50000
#define BN_EPS 1e-5f
#define NTILES_E (EE / 128)      // 6250
#define EDGE_GRID 296

// ---------------------------------------------------------------------------
// Scratch (device globals; no runtime allocation)
// ---------------------------------------------------------------------------
__device__ __align__(16) __half g_h1[(size_t)EE * 128];
__device__ __align__(16) __half g_h2[(size_t)EE * 128];
__device__ __align__(16) __half g_o1[(size_t)NN * 128];
__device__ __align__(16) __half g_o2[(size_t)NN * 128];
__device__ __align__(16) float  g_xw[(size_t)NN * 128];   // x @ w1a[128:256]
__device__ __align__(16) float g_agg[(size_t)NN * 128];
__device__ int   g_cnt[NN];
__device__ float g_sum  [512];                  // 4 layers x 128 col sums
__device__ float g_sumsq[512];                  // 4 layers x 128 col sumsq
__device__ __align__(16) __half g_wt16[98304];  // transposed fp16 weights

// weight slice offsets inside g_wt16 (all [n][k] K-major rows)
#define WT_LO  0        // w1a rows   0..127  (K=128)
#define WT_HI  16384    // w1a rows 128..255  (K=128)
#define WT_W1B 32768    // w1b                (K=128)
#define WT_W2A 49152    // w2a                (K=256)
#define WT_W2B 81920    // w2b                (K=128)

// ---------------------------------------------------------------------------
// Helpers
// ---------------------------------------------------------------------------
__device__ __forceinline__ uint32_t packh2(float a, float b) {
    __half2 h = __floats2half2_rn(a, b);
    return *(uint32_t*)&h;
}

__device__ __forceinline__ uint32_t smem_u32(const void* p) {
    return (uint32_t)__cvta_generic_to_shared(p);
}

__device__ __forceinline__ void cp_async16(uint32_t dst, const void* src) {
    asm volatile("cp.async.cg.shared.global [%0], [%1], 16;"
                 :: "r"(dst), "l"(src));
}
__device__ __forceinline__ void cp_commit() {
    asm volatile("cp.async.commit_group;" ::: "memory");
}
__device__ __forceinline__ void cp_wait0() {
    asm volatile("cp.async.wait_group 0;" ::: "memory");
}

__device__ __forceinline__ void red_add_v4(float* p, float4 v) {
    asm volatile("red.global.add.v4.f32 [%0], {%1,%2,%3,%4};"
                 :: "l"(p), "f"(v.x), "f"(v.y), "f"(v.z), "f"(v.w) : "memory");
}

// ldmatrix: four 8x8 b16 matrices (non-transposed)
__device__ __forceinline__ void ldsm_x4(uint32_t& r0, uint32_t& r1,
                                        uint32_t& r2, uint32_t& r3,
                                        uint32_t addr) {
    asm volatile("ldmatrix.sync.aligned.m8n8.x4.shared.b16 {%0,%1,%2,%3}, [%4];"
                 : "=r"(r0), "=r"(r1), "=r"(r2), "=r"(r3) : "r"(addr));
}

// mma.m16n8k16 fp16 in, fp32 accumulate
__device__ __forceinline__ void mma_f16(float* c, const uint32_t* a,
                                        uint32_t b0, uint32_t b1) {
    asm volatile(
        "mma.sync.aligned.m16n8k16.row.col.f32.f16.f16.f32 "
        "{%0,%1,%2,%3}, {%4,%5,%6,%7}, {%8,%9}, {%0,%1,%2,%3};"
        : "+f"(c[0]), "+f"(c[1]), "+f"(c[2]), "+f"(c[3])
        : "r"(a[0]), "r"(a[1]), "r"(a[2]), "r"(a[3]), "r"(b0), "r"(b1));
}

__device__ __forceinline__ void sts_v4(uint32_t dst, uint4 o) {
    asm volatile("st.shared.v4.b32 [%0], {%1,%2,%3,%4};"
                 :: "r"(dst), "r"(o.x), "r"(o.y), "r"(o.z), "r"(o.w));
}

__device__ __forceinline__ uint32_t h2_affine_relu(uint32_t a, uint32_t s,
                                                   uint32_t f, __half2 z2) {
    __half2 r = __hfma2(*(__half2*)&a, *(__half2*)&s, *(__half2*)&f);
    r = __hmax2(r, z2);
    return *(uint32_t*)&r;
}

// per-lane inline BN fold for 4 consecutive features (f32)
__device__ __forceinline__ void fold4(const float* __restrict__ psum,
                                      const float* __restrict__ psq,
                                      const float* __restrict__ gamma,
                                      const float* __restrict__ beta,
                                      float invM, int c0,
                                      float4& sc, float4& sf)
{
    float4 s = __ldg((const float4*)(psum  + c0));
    float4 q = __ldg((const float4*)(psq   + c0));
    float4 gm = __ldg((const float4*)(gamma + c0));
    float4 bt = __ldg((const float4*)(beta  + c0));
    float m, v;
    m = s.x * invM; v = fmaxf(q.x * invM - m * m, 0.f);
    sc.x = gm.x * rsqrtf(v + BN_EPS); sf.x = bt.x - m * sc.x;
    m = s.y * invM; v = fmaxf(q.y * invM - m * m, 0.f);
    sc.y = gm.y * rsqrtf(v + BN_EPS); sf.y = bt.y - m * sc.y;
    m = s.z * invM; v = fmaxf(q.z * invM - m * m, 0.f);
    sc.z = gm.z * rsqrtf(v + BN_EPS); sf.z = bt.z - m * sc.z;
    m = s.w * invM; v = fmaxf(q.w * invM - m * m, 0.f);
    sc.w = gm.w * rsqrtf(v + BN_EPS); sf.w = bt.w - m * sc.w;
}

// ---------------------------------------------------------------------------
// prep: zero accumulators (vectorized) + transpose/convert weights to f16
// ---------------------------------------------------------------------------
__global__ void prep_kernel(float4* __restrict__ agg4, int* __restrict__ cnt,
                            float* __restrict__ sum, float* __restrict__ sumsq,
                            __half* __restrict__ wt,
                            const float* __restrict__ w1a, const float* __restrict__ w1b,
                            const float* __restrict__ w2a, const float* __restrict__ w2b)
{
    int idx = blockIdx.x * blockDim.x + threadIdx.x;
    if (idx < NN * 32) agg4[idx] = make_float4(0.f, 0.f, 0.f, 0.f);
    if (idx < NN)      cnt[idx] = 0;
    if (idx < 512) { sum[idx] = 0.f; sumsq[idx] = 0.f; }
    if (idx < 98304) {
        float v;
        if (idx < 16384) {                        // w1a lo: k 0..127
            int n = idx >> 7, k = idx & 127;
            v = w1a[k * 128 + n];
        } else if (idx < 32768) {                 // w1a hi: k 128..255
            int i = idx - 16384, n = i >> 7, k = i & 127;
            v = w1a[(128 + k) * 128 + n];
        } else if (idx < 49152) {                 // w1b
            int i = idx - 32768, n = i >> 7, k = i & 127;
            v = w1b[k * 128 + n];
        } else if (idx < 81920) {                 // w2a: K=256
            int i = idx - 49152, n = i >> 8, k = i & 255;
            v = w2a[k * 128 + n];
        } else {                                  // w2b
            int i = idx - 81920, n = i >> 7, k = i & 127;
            v = w2b[k * 128 + n];
        }
        wt[idx] = __float2half_rn(v);
    }
}

// ---------------------------------------------------------------------------
// Shared compute core for persistent edge kernel (K=128, 256B smem rows).
// BN=true applies in-fragment affine+relu using half2 scale/shift tables.
// ---------------------------------------------------------------------------
template<bool BN>
__device__ __forceinline__ void compute_steps(
    uint32_t aB, uint32_t bB, float acc[2][8][4],
    const int* rA, const int* rB, int uHi, int t4,
    const __half2* sScl2, const __half2* sSft2, __half2 z2)
{
#pragma unroll
    for (int step = 0; step < 8; step++) {
        const int unit = step * 2 + uHi;
        uint32_t a[2][4];
#pragma unroll
        for (int mi = 0; mi < 2; mi++)
            ldsm_x4(a[mi][0], a[mi][1], a[mi][2], a[mi][3],
                    aB + (uint32_t)(rA[mi] * 256 + ((unit ^ (rA[mi] & 7)) << 4)));
        if (BN) {
            int b = step * 8 + t4;
            uint32_t cl = *(const uint32_t*)(sScl2 + b);
            uint32_t fl = *(const uint32_t*)(sSft2 + b);
            uint32_t ch = *(const uint32_t*)(sScl2 + b + 4);
            uint32_t fh = *(const uint32_t*)(sSft2 + b + 4);
#pragma unroll
            for (int mi = 0; mi < 2; mi++) {
                a[mi][0] = h2_affine_relu(a[mi][0], cl, fl, z2);
                a[mi][1] = h2_affine_relu(a[mi][1], cl, fl, z2);
                a[mi][2] = h2_affine_relu(a[mi][2], ch, fh, z2);
                a[mi][3] = h2_affine_relu(a[mi][3], ch, fh, z2);
            }
        }
#pragma unroll
        for (int p = 0; p < 4; p++) {
            uint32_t b0, b1, b2, b3;
            ldsm_x4(b0, b1, b2, b3,
                    bB + (uint32_t)(rB[p] * 256 + ((unit ^ (rB[p] & 7)) << 4)));
#pragma unroll
            for (int mi = 0; mi < 2; mi++) {
                mma_f16(acc[mi][2 * p],     a[mi], b0, b2);
                mma_f16(acc[mi][2 * p + 1], a[mi], b1, b3);
            }
        }
    }
}

// stats shuffle-reduce + smem atomics (padless tiles)
__device__ __forceinline__ void stats_reduce(
    float acc[2][8][4], int lane, int t4, int wcc,
    float* sSum, float* sSq)
{
#pragma unroll
    for (int ni = 0; ni < 8; ni++) {
        float s0 = 0, q0 = 0, s1 = 0, q1 = 0;
#pragma unroll
        for (int mi = 0; mi < 2; mi++) {
            float a0 = acc[mi][ni][0], a2 = acc[mi][ni][2];
            float a1 = acc[mi][ni][1], a3 = acc[mi][ni][3];
            s0 += a0 + a2; q0 += a0 * a0 + a2 * a2;
            s1 += a1 + a3; q1 += a1 * a1 + a3 * a3;
        }
#pragma unroll
        for (int off = 4; off < 32; off <<= 1) {
            s0 += __shfl_xor_sync(0xFFFFFFFFu, s0, off);
            q0 += __shfl_xor_sync(0xFFFFFFFFu, q0, off);
            s1 += __shfl_xor_sync(0xFFFFFFFFu, s1, off);
            q1 += __shfl_xor_sync(0xFFFFFFFFu, q1, off);
        }
        if (lane < 4) {
            int c0 = wcc + ni * 8 + 2 * t4;
            atomicAdd(&sSum[c0],     s0); atomicAdd(&sSq[c0],     q0);
            atomicAdd(&sSum[c0 + 1], s1); atomicAdd(&sSq[c0 + 1], q1);
        }
    }
}

// epilogue: acc -> f16 smem staging (256B rows, swizzled) -> coalesced STG
__device__ __forceinline__ void epi_store(
    char* epi, __half* Hout, int bm, int tid, int g, int t4,
    int wr, int wcc, float acc[2][8][4])
{
#pragma unroll
    for (int mi = 0; mi < 2; mi++) {
        int r0 = wr + mi * 16 + g;
        int r1 = r0 + 8;
#pragma unroll
        for (int ni = 0; ni < 8; ni++) {
            int col = wcc + ni * 8 + 2 * t4;
            *(uint32_t*)(epi + r0 * 256 + ((col * 2) ^ ((r0 & 7) << 5))) =
                packh2(acc[mi][ni][0], acc[mi][ni][1]);
            *(uint32_t*)(epi + r1 * 256 + ((col * 2) ^ ((r1 & 7) << 5))) =
                packh2(acc[mi][ni][2], acc[mi][ni][3]);
        }
    }
    __syncthreads();
#pragma unroll
    for (int i = 0; i < 8; i++) {
        int gid = tid + i * 256;
        int row = gid >> 4;
        int seg = gid & 15;
        uint4 v = *(uint4*)(epi + row * 256 + ((seg * 16) ^ ((row & 7) << 5)));
        *(uint4*)(Hout + (size_t)(bm + row) * 128 + seg * 8) = v;
    }
}

// ---------------------------------------------------------------------------
// Persistent edge GEMM 2 (M=128 tiles, round-10 proven): h2 = relu(bn(h1))@w1b
// A via cp.async (f16), BN+relu in-fragment. smem: A0|A1|B (96KB), 2 CTA/SM.
// ---------------------------------------------------------------------------
__launch_bounds__(256, 2)
__global__ void gemm_edge2(
    const __half* __restrict__ h1,
    const float*  __restrict__ psum, const float* __restrict__ psq,
    const float*  __restrict__ gamma, const float* __restrict__ beta,
    const __half* __restrict__ Wt,     // WT_W1B slice
    __half* __restrict__ Hout,
    float* __restrict__ osum, float* __restrict__ osq)
{
    extern __shared__ char dyns[];
    const uint32_t raw   = smem_u32(dyns);
    const uint32_t sbase = (raw + 1023u) & ~1023u;
    char* gbase = dyns + (sbase - raw);
    const uint32_t bB = sbase + 65536u;

    __shared__ __half2 sScl2[64], sSft2[64];
    __shared__ float sSum[128], sSq[128];

    const int tid  = threadIdx.x;
    const int warp = tid >> 5;
    const int lane = tid & 31;
    const int g    = lane >> 2;
    const int t4   = lane & 3;
    const int wr   = (warp & 3) * 32;
    const int wcc  = (warp >> 2) * 64;
    const int uHi  = (lane >> 4);

    if (tid < 128) { sSum[tid] = 0.f; sSq[tid] = 0.f; }
    if (tid < 64) {
        const float invM = 1.0f / EE;
        int k0 = 2 * tid, k1 = k0 + 1;
        float m0 = psum[k0] * invM;
        float v0 = fmaxf(psq[k0] * invM - m0 * m0, 0.f);
        float s0 = gamma[k0] * rsqrtf(v0 + BN_EPS);
        float f0 = beta[k0] - m0 * s0;
        float m1 = psum[k1] * invM;
        float v1 = fmaxf(psq[k1] * invM - m1 * m1, 0.f);
        float s1 = gamma[k1] * rsqrtf(v1 + BN_EPS);
        float f1 = beta[k1] - m1 * s1;
        sScl2[tid] = __floats2half2_rn(s0, s1);
        sSft2[tid] = __floats2half2_rn(f0, f1);
    }

    int rA[2], rB[4];
#pragma unroll
    for (int mi = 0; mi < 2; mi++)
        rA[mi] = wr + mi * 16 + (lane & 7) + ((lane >> 3) & 1) * 8;
#pragma unroll
    for (int p = 0; p < 4; p++)
        rB[p] = wcc + p * 16 + (lane & 7) + ((lane >> 3) & 1) * 8;

    auto cpA = [&](int t, int s) {
        const uint32_t aB = sbase + (uint32_t)s * 32768u;
#pragma unroll
        for (int j = 0; j < 8; j++) {
            int u = tid + j * 256, row = u >> 4, unit = u & 15;
            cp_async16(aB + (uint32_t)(row * 256 + ((unit ^ (row & 7)) << 4)),
                       h1 + (size_t)(t * 128 + row) * 128 + unit * 8);
        }
        cp_commit();
    };

    // prologue: B + A(t0) in one group
#pragma unroll
    for (int j = 0; j < 8; j++) {
        int u = tid + j * 256, n = u >> 4, unit = u & 15;
        cp_async16(bB + (uint32_t)(n * 256 + ((unit ^ (n & 7)) << 4)),
                   Wt + (size_t)n * 128 + unit * 8);
    }
    int t0 = blockIdx.x;
    if (t0 < NTILES_E) {
#pragma unroll
        for (int j = 0; j < 8; j++) {
            int u = tid + j * 256, row = u >> 4, unit = u & 15;
            cp_async16(sbase + (uint32_t)(row * 256 + ((unit ^ (row & 7)) << 4)),
                       h1 + (size_t)(t0 * 128 + row) * 128 + unit * 8);
        }
    }
    cp_commit();

    const __half2 z2 = __floats2half2_rn(0.f, 0.f);
    int i = 0;
    for (int t = t0; t < NTILES_E; t += gridDim.x, i++) {
        const int s  = i & 1;
        const uint32_t aB = sbase + (uint32_t)s * 32768u;
        char* epi = gbase + s * 32768;

        cp_wait0();
        __syncthreads();                              // A(t) (+B first) visible

        int tn = t + gridDim.x;
        if (tn < NTILES_E) cpA(tn, s ^ 1);

        float acc[2][8][4];
#pragma unroll
        for (int mi = 0; mi < 2; mi++)
#pragma unroll
            for (int ni = 0; ni < 8; ni++)
#pragma unroll
                for (int v = 0; v < 4; v++) acc[mi][ni][v] = 0.0f;

        compute_steps<true>(aB, bB, acc, rA, rB, uHi, t4, sScl2, sSft2, z2);
        stats_reduce(acc, lane, t4, wcc, sSum, sSq);
        __syncthreads();                              // A_s reads done
        epi_store(epi, Hout, t * 128, tid, g, t4, wr, wcc, acc);
    }

    __syncthreads();
    if (tid < 128) {
        atomicAdd(osum + tid, sSum[tid]);
        atomicAdd(osq  + tid, sSq[tid]);
    }
}

// ---------------------------------------------------------------------------
// Tiled GEMM (round-8 proven): out[M,128] = A[M,K] @ W[K,128] + fused stats.
// MODE 0: A = message (K=128); epilogue acc += xw[row[r]] BEFORE stats;
//         prologue also accumulates cnt histogram for this tile's edges
// MODE 1: A = relu(prev*scale + shift)     (K=128, f16 source)
// MODE 2: A = concat(x, agg_sum*inv_cnt)   (K=256, f32 sources)
// MODE 3: A = x (K=128, f32); plain gemm, f32 out, no stats (xw precompute)
// ---------------------------------------------------------------------------
template<int MODE>
__launch_bounds__(256, 2)
__global__ void gemm_f16(
    const float*  __restrict__ A0f,
    const float*  __restrict__ A1f,
    const __half* __restrict__ A0h,
    const float*  __restrict__ xw,
    const int*    __restrict__ ridx,
    const int*    __restrict__ cidx,   // MODE 0: edge col indices (cnt histo)
    const int*    __restrict__ cnt,
    int*          __restrict__ cnt_out,
    const float*  __restrict__ psum,
    const float*  __restrict__ psq,
    const float*  __restrict__ gamma,
    const float*  __restrict__ beta,
    float         invPrevM,
    const __half* __restrict__ Wt,
    __half* __restrict__ Hout,
    float*  __restrict__ Hout32,
    int M,
    float* __restrict__ osum,
    float* __restrict__ osq)
{
    constexpr int K   = (MODE == 2) ? 256 : 128;
    constexpr int NIT = K / 64;

    extern __shared__ char dyns[];
    const uint32_t raw   = smem_u32(dyns);
    const uint32_t sbase = (raw + 1023u) & ~1023u;
    char* gbase = dyns + (sbase - raw);

    __shared__ int   sRow[128];
    __shared__ float sInv[128], sScl[128], sSft[128];
    __shared__ float sSum[128], sSq[128];

    const int tid  = threadIdx.x;
    const int warp = tid >> 5;
    const int lane = tid & 31;
    const int bm   = blockIdx.x * 128;

    if (tid < 128) { sSum[tid] = 0.f; sSq[tid] = 0.f; }
    if (MODE == 0 && tid < 128) {
        sRow[tid] = ridx[bm + tid];
        atomicAdd(cnt_out + cidx[bm + tid], 1);   // cnt histogram (hidden
    }                                             // under the DRAM-bound loop)
    if (MODE == 2 && tid < 128) {
        int r = bm + tid;
        int c = (r < M) ? cnt[r] : 1;
        sInv[tid] = 1.0f / (float)(c > 1 ? c : 1);
    }
    if (MODE == 1 && tid < 128) {
        float m  = psum[tid] * invPrevM;
        float v  = fmaxf(psq[tid] * invPrevM - m * m, 0.f);
        float sc = gamma[tid] * rsqrtf(v + BN_EPS);
        sScl[tid] = sc;
        sSft[tid] = beta[tid] - m * sc;
    }
    __syncthreads();

    auto ldgA = [&](int it, float4* pf, uint4* ph) {
        const int k0 = it * 64;
#pragma unroll
        for (int j = 0; j < 4; j++) {
            int u = tid + j * 256, row = u >> 3, unit = u & 7;
            int kg = k0 + unit * 8;
            int rg = bm + row;
            if (MODE == 1) {
                ph[j] = (rg < M) ? *(const uint4*)(A0h + (size_t)rg * 128 + kg)
                                 : make_uint4(0, 0, 0, 0);
            } else if (MODE == 0) {
                const float* src = A0f + (size_t)rg * 128 + kg;  // EE % 128 == 0
                pf[2 * j]     = *(const float4*)src;
                pf[2 * j + 1] = *(const float4*)(src + 4);
            } else {
                if (rg < M) {
                    const float* src = (MODE == 3 || kg < 128)
                        ? (A0f + (size_t)rg * 128 + kg)
                        : (A1f + (size_t)rg * 128 + (kg - 128));
                    pf[2 * j]     = *(const float4*)src;
                    pf[2 * j + 1] = *(const float4*)(src + 4);
                } else {
                    pf[2 * j]     = make_float4(0, 0, 0, 0);
                    pf[2 * j + 1] = make_float4(0, 0, 0, 0);
                }
            }
        }
    };

    auto stsA = [&](int it, int s, const float4* pf, const uint4* ph) {
        const int k0 = it * 64;
        const uint32_t aB = sbase + (uint32_t)s * 16384u;
#pragma unroll
        for (int j = 0; j < 4; j++) {
            int u = tid + j * 256, row = u >> 3, unit = u & 7;
            int kg = k0 + unit * 8;
            int rg = bm + row;
            uint32_t dst = aB + (uint32_t)(row * 128 + ((unit ^ (row & 7)) << 4));
            uint4 o;
            if (MODE == 0) {
                float4 p = pf[2 * j], q = pf[2 * j + 1];
                o.x = packh2(p.x, p.y); o.y = packh2(p.z, p.w);
                o.z = packh2(q.x, q.y); o.w = packh2(q.z, q.w);
            } else if (MODE == 1) {
                if (rg < M) {
                    uint4 rv = ph[j];
                    float4 sc0 = *(const float4*)(sScl + kg);
                    float4 sc1 = *(const float4*)(sScl + kg + 4);
                    float4 sf0 = *(const float4*)(sSft + kg);
                    float4 sf1 = *(const float4*)(sSft + kg + 4);
                    float2 v0 = __half22float2(*(__half2*)&rv.x);
                    float2 v1 = __half22float2(*(__half2*)&rv.y);
                    float2 v2 = __half22float2(*(__half2*)&rv.z);
                    float2 v3 = __half22float2(*(__half2*)&rv.w);
                    o.x = packh2(fmaxf(fmaf(v0.x, sc0.x, sf0.x), 0.f),
                                 fmaxf(fmaf(v0.y, sc0.y, sf0.y), 0.f));
                    o.y = packh2(fmaxf(fmaf(v1.x, sc0.z, sf0.z), 0.f),
                                 fmaxf(fmaf(v1.y, sc0.w, sf0.w), 0.f));
                    o.z = packh2(fmaxf(fmaf(v2.x, sc1.x, sf1.x), 0.f),
                                 fmaxf(fmaf(v2.y, sc1.y, sf1.y), 0.f));
                    o.w = packh2(fmaxf(fmaf(v3.x, sc1.z, sf1.z), 0.f),
                                 fmaxf(fmaf(v3.y, sc1.w, sf1.w), 0.f));
                } else {
                    o = make_uint4(0, 0, 0, 0);
                }
            } else {
                if (rg < M) {
                    float4 p = pf[2 * j], q = pf[2 * j + 1];
                    if (MODE == 2 && kg >= 128) {
                        float iv = sInv[row];
                        p.x *= iv; p.y *= iv; p.z *= iv; p.w *= iv;
                        q.x *= iv; q.y *= iv; q.z *= iv; q.w *= iv;
                    }
                    o.x = packh2(p.x, p.y); o.y = packh2(p.z, p.w);
                    o.z = packh2(q.x, q.y); o.w = packh2(q.z, q.w);
                } else {
                    o = make_uint4(0, 0, 0, 0);
                }
            }
            sts_v4(dst, o);
        }
    };

    auto cpB = [&](int it, int s) {
        const int k0 = it * 64;
        const uint32_t bB = sbase + 32768u + (uint32_t)s * 16384u;
#pragma unroll
        for (int j = 0; j < 4; j++) {
            int u = tid + j * 256, n = u >> 3, unit = u & 7;
            uint32_t dst = bB + (uint32_t)(n * 128 + ((unit ^ (n & 7)) << 4));
            cp_async16(dst, Wt + (size_t)n * K + k0 + unit * 8);
        }
        cp_commit();
    };

    float acc[2][8][4];
#pragma unroll
    for (int mi = 0; mi < 2; mi++)
#pragma unroll
        for (int ni = 0; ni < 8; ni++)
#pragma unroll
            for (int v = 0; v < 4; v++) acc[mi][ni][v] = 0.0f;

    const int g   = lane >> 2;
    const int t4  = lane & 3;
    const int wm  = warp & 3;
    const int wn  = warp >> 2;
    const int wr  = wm * 32;
    const int wcc = wn * 64;

    int rA[2], rB[4];
#pragma unroll
    for (int mi = 0; mi < 2; mi++)
        rA[mi] = wr + mi * 16 + (lane & 7) + ((lane >> 3) & 1) * 8;
#pragma unroll
    for (int p = 0; p < 4; p++)
        rB[p] = wcc + p * 16 + (lane & 7) + ((lane >> 3) & 1) * 8;
    const int uHi = (lane >> 4);

    {
        float4 pf[8]; uint4 ph[4];
        ldgA(0, pf, ph);
        stsA(0, 0, pf, ph);
        cpB(0, 0);
    }

#pragma unroll 1
    for (int it = 0; it < NIT; it++) {
        const int s = it & 1;
        cp_wait0();
        __syncthreads();

        float4 pf[8]; uint4 ph[4];
        const bool more = (it + 1 < NIT);
        if (more) {
            ldgA(it + 1, pf, ph);
            cpB(it + 1, s ^ 1);
        }

        const uint32_t aB = sbase + (uint32_t)s * 16384u;
        const uint32_t bB = sbase + 32768u + (uint32_t)s * 16384u;

#pragma unroll
        for (int step = 0; step < 4; step++) {
            const int unit = step * 2 + uHi;
            uint32_t a[2][4];
#pragma unroll
            for (int mi = 0; mi < 2; mi++)
                ldsm_x4(a[mi][0], a[mi][1], a[mi][2], a[mi][3],
                        aB + (uint32_t)(rA[mi] * 128 + ((unit ^ (rA[mi] & 7)) << 4)));
#pragma unroll
            for (int p = 0; p < 4; p++) {
                uint32_t b0, b1, b2, b3;
                ldsm_x4(b0, b1, b2, b3,
                        bB + (uint32_t)(rB[p] * 128 + ((unit ^ (rB[p] & 7)) << 4)));
#pragma unroll
                for (int mi = 0; mi < 2; mi++) {
                    mma_f16(acc[mi][2 * p],     a[mi], b0, b2);
                    mma_f16(acc[mi][2 * p + 1], a[mi], b1, b3);
                }
            }
        }

        if (more) stsA(it + 1, s ^ 1, pf, ph);
    }

    // ---- MODE 0: add per-node xw contribution BEFORE stats ----
    if (MODE == 0) {
#pragma unroll
        for (int mi = 0; mi < 2; mi++) {
            const float* x0 = xw + (size_t)sRow[wr + mi * 16 + g]     * 128;
            const float* x1 = xw + (size_t)sRow[wr + mi * 16 + g + 8] * 128;
#pragma unroll
            for (int ni = 0; ni < 8; ni++) {
                int col = wcc + ni * 8 + 2 * t4;
                float2 u0 = *(const float2*)(x0 + col);
                float2 u1 = *(const float2*)(x1 + col);
                acc[mi][ni][0] += u0.x; acc[mi][ni][1] += u0.y;
                acc[mi][ni][2] += u1.x; acc[mi][ni][3] += u1.y;
            }
        }
    }

    if (MODE != 3) {
#pragma unroll
        for (int ni = 0; ni < 8; ni++) {
            float s0 = 0, q0 = 0, s1 = 0, q1 = 0;
#pragma unroll
            for (int mi = 0; mi < 2; mi++) {
                float a0 = acc[mi][ni][0], a2 = acc[mi][ni][2];
                float a1 = acc[mi][ni][1], a3 = acc[mi][ni][3];
                s0 += a0 + a2; q0 += a0 * a0 + a2 * a2;
                s1 += a1 + a3; q1 += a1 * a1 + a3 * a3;
            }
#pragma unroll
            for (int off = 4; off < 32; off <<= 1) {
                s0 += __shfl_xor_sync(0xFFFFFFFFu, s0, off);
                q0 += __shfl_xor_sync(0xFFFFFFFFu, q0, off);
                s1 += __shfl_xor_sync(0xFFFFFFFFu, s1, off);
                q1 += __shfl_xor_sync(0xFFFFFFFFu, q1, off);
            }
            if (lane < 4) {
                int c0 = wcc + ni * 8 + 2 * t4;
                atomicAdd(&sSum[c0],     s0); atomicAdd(&sSq[c0],     q0);
                atomicAdd(&sSum[c0 + 1], s1); atomicAdd(&sSq[c0 + 1], q1);
            }
        }
    }

    __syncthreads();
    char* epi = gbase;

    if (MODE == 3) {
#pragma unroll
        for (int mi = 0; mi < 2; mi++) {
            int r0 = wr + mi * 16 + g;
            int r1 = r0 + 8;
#pragma unroll
            for (int ni = 0; ni < 8; ni++) {
                int col = wcc + ni * 8 + 2 * t4;
                *(float2*)(epi + r0 * 512 + ((col * 4) ^ ((r0 & 7) << 5))) =
                    make_float2(acc[mi][ni][0], acc[mi][ni][1]);
                *(float2*)(epi + r1 * 512 + ((col * 4) ^ ((r1 & 7) << 5))) =
                    make_float2(acc[mi][ni][2], acc[mi][ni][3]);
            }
        }
        __syncthreads();
#pragma unroll
        for (int i = 0; i < 16; i++) {
            int gid = tid + i * 256;
            int row = gid >> 5;
            int seg = gid & 31;
            if (bm + row < M) {
                uint4 v = *(uint4*)(epi + row * 512 + ((seg * 16) ^ ((row & 7) << 5)));
                *(uint4*)(Hout32 + (size_t)(bm + row) * 128 + seg * 4) = v;
            }
        }
        return;
    }

#pragma unroll
    for (int mi = 0; mi < 2; mi++) {
        int r0 = wr + mi * 16 + g;
        int r1 = r0 + 8;
#pragma unroll
        for (int ni = 0; ni < 8; ni++) {
            int col = wcc + ni * 8 + 2 * t4;
            *(uint32_t*)(epi + r0 * 256 + ((col * 2) ^ ((r0 & 7) << 5))) =
                packh2(acc[mi][ni][0], acc[mi][ni][1]);
            *(uint32_t*)(epi + r1 * 256 + ((col * 2) ^ ((r1 & 7) << 5))) =
                packh2(acc[mi][ni][2], acc[mi][ni][3]);
        }
    }
    __syncthreads();
#pragma unroll
    for (int i = 0; i < 8; i++) {
        int gid = tid + i * 256;
        int row = gid >> 4;
        int seg = gid & 15;
        if (bm + row < M) {
            uint4 v = *(uint4*)(epi + row * 256 + ((seg * 16) ^ ((row & 7) << 5)));
            *(uint4*)(Hout + (size_t)(bm + row) * 128 + seg * 8) = v;
        }
    }

    if (tid < 128) {
        atomicAdd(osum + tid, sSum[tid]);
        atomicAdd(osq  + tid, sSq[tid]);
    }
}

// ---------------------------------------------------------------------------
// Scatter: agg[col[e]] += relu(bn(h2_f16[e]))  (cnt already built by edge1)
// 8 edges per warp, 64 edges per block; BN fold computed inline per lane.
// ---------------------------------------------------------------------------
__global__ void scatter_kernel(const __half* __restrict__ h2,
                               const int* __restrict__ col,
                               const float* __restrict__ psum,
                               const float* __restrict__ psq,
                               const float* __restrict__ gamma,
                               const float* __restrict__ beta,
                               float* __restrict__ agg)
{
    const int t    = threadIdx.x;        // 256
    const int warp = t >> 5;
    const int lane = t & 31;

    float4 sc, sf;
    fold4(psum, psq, gamma, beta, 1.0f / EE, lane * 4, sc, sf);

    const int e0 = blockIdx.x * 64 + warp * 8;
#pragma unroll
    for (int i = 0; i < 8; i++) {
        int e = e0 + i;
        int c = __ldg(col + e);
        uint2 rawv = *(const uint2*)(h2 + (size_t)e * 128 + lane * 4);
        float2 a = __half22float2(*(__half2*)&rawv.x);
        float2 b = __half22float2(*(__half2*)&rawv.y);
        float4 v;
        v.x = fmaxf(fmaf(a.x, sc.x, sf.x), 0.f);
        v.y = fmaxf(fmaf(a.y, sc.y, sf.y), 0.f);
        v.z = fmaxf(fmaf(b.x, sc.z, sf.z), 0.f);
        v.w = fmaxf(fmaf(b.y, sc.w, sf.w), 0.f);
        red_add_v4(agg + (size_t)c * 128 + lane * 4, v);
    }
}

// ---------------------------------------------------------------------------
// Final: o = relu(bn(o2)); attn = sigmoid(o @ wa + ba)
// One warp per node (8 nodes/block); BN fold computed inline per lane.
// ---------------------------------------------------------------------------
__global__ void output_kernel(const __half* __restrict__ o2,
                              const float* __restrict__ psum,
                              const float* __restrict__ psq,
                              const float* __restrict__ gamma,
                              const float* __restrict__ beta,
                              const float* __restrict__ wa,
                              const float* __restrict__ ba,
                              float* __restrict__ out)
{
    const int warp = threadIdx.x >> 5;
    const int lane = threadIdx.x & 31;
    const int n    = blockIdx.x * 8 + warp;   // NN % 8 == 0

    float4 sc, sf;
    fold4(psum, psq, gamma, beta, 1.0f / NN, lane * 4, sc, sf);
    const float4 w = __ldg((const float4*)(wa + lane * 4));

    uint2 rawv = *(const uint2*)(o2 + (size_t)n * 128 + lane * 4);
    float2 a = __half22float2(*(__half2*)&rawv.x);
    float2 b = __half22float2(*(__half2*)&rawv.y);
    float4 v;
    v.x = fmaxf(fmaf(a.x, sc.x, sf.x), 0.f);
    v.y = fmaxf(fmaf(a.y, sc.y, sf.y), 0.f);
    v.z = fmaxf(fmaf(b.x, sc.z, sf.z), 0.f);
    v.w = fmaxf(fmaf(b.y, sc.w, sf.w), 0.f);
    *(float4*)(out + (size_t)n * 128 + lane * 4) = v;

    float p = v.x * w.x + v.y * w.y + v.z * w.z + v.w * w.w;
#pragma unroll
    for (int off = 16; off > 0; off >>= 1)
        p += __shfl_xor_sync(0xFFFFFFFFu, p, off);
    if (lane == 0)
        out[(size_t)NN * 128 + n] = 1.0f / (1.0f + expf(-(p + __ldg(ba))));
}

// ---------------------------------------------------------------------------
// Launch
// ---------------------------------------------------------------------------
#define GEMM_SMEM (65536 + 1024)
#define EDGE_SMEM (98304 + 1024)

extern "C" void kernel_launch(void* const* d_in, const int* in_sizes, int n_in,
                              void* d_out, int out_size)
{
    const float* x       = (const float*)d_in[0];
    const int*   ei      = (const int*)  d_in[1];   // [2,E]: row then col
    const float* message = (const float*)d_in[2];
    const float* w1a  = (const float*)d_in[3];
    const float* g1a  = (const float*)d_in[5];
    const float* be1a = (const float*)d_in[6];
    const float* w1b  = (const float*)d_in[7];
    const float* g1b  = (const float*)d_in[9];
    const float* be1b = (const float*)d_in[10];
    const float* w2a  = (const float*)d_in[11];
    const float* g2a  = (const float*)d_in[13];
    const float* be2a = (const float*)d_in[14];
    const float* w2b  = (const float*)d_in[15];
    const float* g2b  = (const float*)d_in[17];
    const float* be2b = (const float*)d_in[18];
    const float* wa   = (const float*)d_in[19];
    const float* ba   = (const float*)d_in[20];
    float* out = (float*)d_out;

    __half *h1, *h2, *o1, *o2, *wt;
    float *agg, *sum, *sumsq, *xw;
    int* cnt;
    cudaGetSymbolAddress((void**)&h1,    g_h1);
    cudaGetSymbolAddress((void**)&h2,    g_h2);
    cudaGetSymbolAddress((void**)&o1,    g_o1);
    cudaGetSymbolAddress((void**)&o2,    g_o2);
    cudaGetSymbolAddress((void**)&xw,    g_xw);
    cudaGetSymbolAddress((void**)&agg,   g_agg);
    cudaGetSymbolAddress((void**)&cnt,   g_cnt);
    cudaGetSymbolAddress((void**)&sum,   g_sum);
    cudaGetSymbolAddress((void**)&sumsq, g_sumsq);
    cudaGetSymbolAddress((void**)&wt,    g_wt16);

    const int* row = ei;
    const int* col = ei + EE;

    static bool attr_done = false;
    if (!attr_done) {
        cudaFuncSetAttribute(gemm_f16<0>, cudaFuncAttributeMaxDynamicSharedMemorySize, GEMM_SMEM);
        cudaFuncSetAttribute(gemm_f16<1>, cudaFuncAttributeMaxDynamicSharedMemorySize, GEMM_SMEM);
        cudaFuncSetAttribute(gemm_f16<2>, cudaFuncAttributeMaxDynamicSharedMemorySize, GEMM_SMEM);
        cudaFuncSetAttribute(gemm_f16<3>, cudaFuncAttributeMaxDynamicSharedMemorySize, GEMM_SMEM);
        cudaFuncSetAttribute(gemm_edge2, cudaFuncAttributeMaxDynamicSharedMemorySize, EDGE_SMEM);
        attr_done = true;
    }

    prep_kernel<<<(NN * 32 + 1023) / 1024, 1024>>>((float4*)agg, cnt, sum, sumsq,
                                                   wt, w1a, w1b, w2a, w2b);

    // xw = x @ w1a[128:256]  (f32 out, no stats)
    gemm_f16<3><<<(NN + 127) / 128, 256, GEMM_SMEM>>>(x, nullptr, nullptr, nullptr,
                                 nullptr, nullptr, nullptr, nullptr,
                                 nullptr, nullptr, nullptr, nullptr, 0.f,
                                 wt + WT_HI, nullptr, xw, NN, nullptr, nullptr);

    // edge layer 1: h1 = message @ w1a_lo + xw[row]  (+slot 0, + cnt histo)
    gemm_f16<0><<<EE / 128, 256, GEMM_SMEM>>>(message, nullptr, nullptr, xw, row,
                                 col, nullptr, cnt,
                                 nullptr, nullptr, nullptr, nullptr, 0.f,
                                 wt + WT_LO, h1, nullptr, EE, sum + 0, sumsq + 0);

    // edge layer 2 (persistent M=128, proven): h2 = relu(bn1a(h1)) @ w1b
    gemm_edge2<<<EDGE_GRID, 256, EDGE_SMEM>>>(h1, sum + 0, sumsq + 0, g1a, be1a,
                                              wt + WT_W1B, h2, sum + 128, sumsq + 128);

    // scatter (8 edges/warp) with inline bn1b fold; cnt already built
    scatter_kernel<<<EE / 64, 256>>>(h2, col, sum + 128, sumsq + 128, g1b, be1b,
                                     agg);

    // node layer 1: o1 = concat(x, agg/cnt) @ w2a        (+stats slot 2)
    gemm_f16<2><<<(NN + 127) / 128, 256, GEMM_SMEM>>>(x, agg, nullptr, nullptr,
                                 nullptr, nullptr, cnt, nullptr,
                                 nullptr, nullptr, nullptr, nullptr, 0.f,
                                 wt + WT_W2A, o1, nullptr, NN, sum + 256, sumsq + 256);

    // node layer 2: o2 = relu(bn2a(o1)) @ w2b            (+stats slot 3)
    gemm_f16<1><<<(NN + 127) / 128, 256, GEMM_SMEM>>>(nullptr, nullptr, o1, nullptr,
                                 nullptr, nullptr, nullptr, nullptr,
                                 sum + 256, sumsq + 256, g2a, be2a, 1.0f / NN,
                                 wt + WT_W2B, o2, nullptr, NN, sum + 384, sumsq + 384);

    // output (warp per node) with inline bn2b fold: o + attn
    output_kernel<<<NN / 8, 256>>>(o2, sum + 384, sumsq + 384, g2b, be2b,
                                   wa, ba, out);
}